// round 10
// baseline (speedup 1.0000x reference)
#include <cuda_runtime.h>
#include <cuda_fp16.h>
#include <stdint.h>
#include <math.h>

#define NN 200000
#define NE 6400000
#define NG 64
#define NB_SCAN 782   // ceil(NN/256); all blocks resident

// ---- device scratch (static, no runtime allocation) ----
__device__ int    g_count[NN];        // in-degree
__device__ int    g_cursor[NN];       // scatter cursor
__device__ int    g_off[NN];          // CSR offsets (exclusive scan)
__device__ int    g_bsum[1024];       // scan block totals
__device__ int    g_sync[4];          // global sync counters
__device__ uint4  g_sorted[NE];       // {src, ef01(half2), ef23(half2), 0} sorted by dst
__device__ __half g_nfh[NN * 8];      // node_feat as half, padded to 8/row (16B)
__device__ __half g_h1h[NN * 32];     // layer-1 output (fp16, 12.8MB)
__device__ float  g_pooled[NG * 32];

// ---------------- setup: zero scratch + pad/convert node features ----------------
__global__ void setup_kernel(const float* __restrict__ node_feat) {
    int i = blockIdx.x * blockDim.x + threadIdx.x;
    if (i < NN * 8) {
        int n = i >> 3, k = i & 7;
        g_nfh[i] = __float2half_rn((k < 7) ? node_feat[n * 7 + k] : 0.0f);
    }
    if (i < NN) { g_count[i] = 0; g_cursor[i] = 0; }
    if (i < NG * 32) g_pooled[i] = 0.0f;
    if (i < 4) g_sync[i] = 0;
}

__device__ __forceinline__ unsigned int pack_h2(float a, float b) {
    __half2 h = __floats2half2_rn(a, b);
    return *(unsigned int*)&h;
}

__device__ __forceinline__ void gsync(int idx) {
    __syncthreads();
    __threadfence();
    if (threadIdx.x == 0) {
        atomicAdd(&g_sync[idx], 1);
        while (atomicAdd(&g_sync[idx], 0) < NB_SCAN) { }
    }
    __syncthreads();
}

// ---------------- persistent sort: hist -> scan -> scatter ----------------
__global__ void sort_kernel(const int4* __restrict__ src4,
                            const int4* __restrict__ dst4,
                            const float4* __restrict__ ef4) {
    __shared__ int s[256];
    int t = threadIdx.x;
    int b = blockIdx.x;
    int i = b * 256 + t;
    const int nquads = NE / 4;

    // --- phase 0: histogram of dst ---
    for (int q = b * 256 + t; q < nquads; q += NB_SCAN * 256) {
        int4 d = dst4[q];
        atomicAdd(&g_count[d.x], 1);
        atomicAdd(&g_count[d.y], 1);
        atomicAdd(&g_count[d.z], 1);
        atomicAdd(&g_count[d.w], 1);
    }
    gsync(0);

    // --- phase 1: block-local inclusive scan of degrees ---
    int v = (i < NN) ? g_count[i] : 0;
    s[t] = v;
    __syncthreads();
    for (int off = 1; off < 256; off <<= 1) {
        int add = (t >= off) ? s[t - off] : 0;
        __syncthreads();
        s[t] += add;
        __syncthreads();
    }
    int local_excl = s[t] - v;
    if (t == 255) {
        g_bsum[b] = s[255];
        __threadfence();
        atomicAdd(&g_sync[1], 1);
    }
    if (t == 0) { while (atomicAdd(&g_sync[1], 0) < NB_SCAN) { } }
    __syncthreads();

    // --- phase 2: block prefix from published totals ---
    int pre = 0;
    for (int k = t; k < b; k += 256) pre += g_bsum[k];
    s[t] = pre;
    __syncthreads();
    for (int o = 128; o; o >>= 1) {
        if (t < o) s[t] += s[t + o];
        __syncthreads();
    }
    if (i < NN) g_off[i] = s[0] + local_excl;

    gsync(2);

    // --- phase 3: grid-stride scatter of packed {src, fp16 edge_feat} ---
    for (int q = b * 256 + t; q < nquads; q += NB_SCAN * 256) {
        int4 sv = src4[q];
        int4 dv = dst4[q];
        float4 e0 = ef4[q * 4 + 0];
        float4 e1 = ef4[q * 4 + 1];
        float4 e2 = ef4[q * 4 + 2];
        float4 e3 = ef4[q * 4 + 3];
        uint4 w;
        w.w = 0u;

        int p0 = g_off[dv.x] + atomicAdd(&g_cursor[dv.x], 1);
        w.x = (unsigned int)sv.x; w.y = pack_h2(e0.x, e0.y); w.z = pack_h2(e0.z, e0.w);
        g_sorted[p0] = w;
        int p1 = g_off[dv.y] + atomicAdd(&g_cursor[dv.y], 1);
        w.x = (unsigned int)sv.y; w.y = pack_h2(e1.x, e1.y); w.z = pack_h2(e1.z, e1.w);
        g_sorted[p1] = w;
        int p2 = g_off[dv.z] + atomicAdd(&g_cursor[dv.z], 1);
        w.x = (unsigned int)sv.z; w.y = pack_h2(e2.x, e2.y); w.z = pack_h2(e2.z, e2.w);
        g_sorted[p2] = w;
        int p3 = g_off[dv.w] + atomicAdd(&g_cursor[dv.w], 1);
        w.x = (unsigned int)sv.w; w.y = pack_h2(e3.x, e3.y); w.z = pack_h2(e3.z, e3.w);
        g_sorted[p3] = w;
    }
}

// ---------------- layer 1: sequential edge stream + one fp16 nf gather ----------------
__global__ void node1_kernel(const float* __restrict__ W1a, const float* __restrict__ b1a,
                             const float* __restrict__ W1b, const float* __restrict__ b1b) {
    __shared__ float sW1a[11 * 32];
    __shared__ float sW1b[32 * 32];
    __shared__ float sb1a[32];
    __shared__ float sb1b[32];
    int tid = threadIdx.x;
    for (int k = tid; k < 11 * 32; k += blockDim.x) sW1a[k] = W1a[k];
    for (int k = tid; k < 32 * 32; k += blockDim.x) sW1b[k] = W1b[k];
    if (tid < 32) { sb1a[tid] = b1a[tid]; sb1b[tid] = b1b[tid]; }
    __syncthreads();

    int warp = tid >> 5;
    int lane = tid & 31;
    int n = blockIdx.x * (blockDim.x >> 5) + warp;
    if (n >= NN) return;

    int start = g_off[n];
    int deg   = g_count[n];

    float acc[11];
#pragma unroll
    for (int k = 0; k < 11; k++) acc[k] = 0.0f;

    const uint4* nfq = (const uint4*)g_nfh;
    for (int j = lane; j < deg; j += 32) {
        uint4 p = __ldg(&g_sorted[start + j]);   // coalesced 16B stream
        __half2 h01 = *(__half2*)&p.y;
        __half2 h23 = *(__half2*)&p.z;
        float2 e01 = __half22float2(h01);
        float2 e23 = __half22float2(h23);
        acc[0] += e01.x; acc[1] += e01.y; acc[2] += e23.x; acc[3] += e23.y;
        uint4 nf = __ldg(&nfq[p.x]);             // ONE 16B gather (L2-resident)
        __half2 n0 = *(__half2*)&nf.x;
        __half2 n1 = *(__half2*)&nf.y;
        __half2 n2 = *(__half2*)&nf.z;
        __half2 n3 = *(__half2*)&nf.w;
        float2 f0 = __half22float2(n0);
        float2 f1 = __half22float2(n1);
        float2 f2 = __half22float2(n2);
        float2 f3 = __half22float2(n3);
        acc[4] += f0.x; acc[5] += f0.y;
        acc[6] += f1.x; acc[7] += f1.y;
        acc[8] += f2.x; acc[9] += f2.y;
        acc[10] += f3.x;
    }

#pragma unroll
    for (int off = 16; off; off >>= 1) {
#pragma unroll
        for (int k = 0; k < 11; k++)
            acc[k] += __shfl_xor_sync(0xffffffffu, acc[k], off);
    }

    float invd = 1.0f / fmaxf((float)deg, 1.0f);

    float y = sb1a[lane];
#pragma unroll
    for (int k = 0; k < 11; k++)
        y = fmaf(acc[k] * invd, sW1a[k * 32 + lane], y);
    y = fmaxf(y, 0.0f);

    float z = sb1b[lane];
#pragma unroll
    for (int k = 0; k < 32; k++) {
        float yk = __shfl_sync(0xffffffffu, y, k);
        z = fmaf(yk, sW1b[k * 32 + lane], z);
    }
    z = fmaxf(z, 0.0f);

    g_h1h[n * 32 + lane] = __float2half_rn(z);
}

// ---------------- layer 2: 2 nodes/warp, pair-layout gather + float4-weight MLP ----------------
__global__ void node2_kernel(const float* __restrict__ W2a, const float* __restrict__ b2a,
                             const float* __restrict__ W2b, const float* __restrict__ b2b,
                             const int* __restrict__ graph_ids) {
    // weights pre-swizzled: sW[kp*16+fl] = {W[2kp][2fl], W[2kp+1][2fl], W[2kp][2fl+1], W[2kp+1][2fl+1]}
    __shared__ float4 sWa[256];
    __shared__ float4 sWb[256];
    __shared__ float2 sba[16];
    __shared__ float2 sbb[16];
    int tid = threadIdx.x;
    for (int idx = tid; idx < 256; idx += blockDim.x) {
        int kp = idx >> 4, f = idx & 15;
        sWa[idx] = make_float4(W2a[(2 * kp) * 32 + 2 * f],     W2a[(2 * kp + 1) * 32 + 2 * f],
                               W2a[(2 * kp) * 32 + 2 * f + 1], W2a[(2 * kp + 1) * 32 + 2 * f + 1]);
        sWb[idx] = make_float4(W2b[(2 * kp) * 32 + 2 * f],     W2b[(2 * kp + 1) * 32 + 2 * f],
                               W2b[(2 * kp) * 32 + 2 * f + 1], W2b[(2 * kp + 1) * 32 + 2 * f + 1]);
    }
    if (tid < 16) {
        sba[tid] = make_float2(b2a[2 * tid], b2a[2 * tid + 1]);
        sbb[tid] = make_float2(b2b[2 * tid], b2b[2 * tid + 1]);
    }
    __syncthreads();

    int warp = tid >> 5;
    int lane = tid & 31;
    int half = lane >> 4;        // which node of the pair
    int fl   = lane & 15;        // feature-pair index
    int base = lane & 16;        // shfl source base for own half

    int n = blockIdx.x * 16 + warp * 2 + half;   // NN divisible by 16
    int start = g_off[n];
    int deg   = g_count[n];

    int myRounds = (deg + 7) >> 3;
    int otherRounds = __shfl_xor_sync(0xffffffffu, myRounds, 16);
    int rounds = myRounds > otherRounds ? myRounds : otherRounds;

    const __half2* h1p = (const __half2*)g_h1h;
    const unsigned int* sortedx = (const unsigned int*)g_sorted;  // .x at stride 4

    float2 acc = make_float2(0.0f, 0.0f);
    for (int r = 0; r < rounds; r++) {
        int jb = r * 8;
        int idx = 0;
        if (fl < 8) {
            int pos = start + jb + fl;
            if (pos >= NE) pos = 0;          // clamped; use predicated below
            idx = (int)sortedx[(size_t)pos * 4];
        }
#pragma unroll
        for (int e = 0; e < 8; e++) {
            int srcE = __shfl_sync(0xffffffffu, idx, base + e);
            if (jb + e < deg) {              // uniform per half-warp
                float2 v = __half22float2(__ldg(&h1p[srcE * 16 + fl]));
                acc.x += v.x;
                acc.y += v.y;
            }
        }
    }

    float invd = 1.0f / fmaxf((float)deg, 1.0f);
    float2 x2 = make_float2(acc.x * invd, acc.y * invd);

    // layer a: y[2fl],y[2fl+1] for own node
    float2 y2 = sba[fl];
#pragma unroll
    for (int kp = 0; kp < 16; kp++) {
        float xx = __shfl_sync(0xffffffffu, x2.x, base + kp);
        float xy = __shfl_sync(0xffffffffu, x2.y, base + kp);
        float4 w = sWa[kp * 16 + fl];
        y2.x = fmaf(xx, w.x, y2.x);
        y2.x = fmaf(xy, w.y, y2.x);
        y2.y = fmaf(xx, w.z, y2.y);
        y2.y = fmaf(xy, w.w, y2.y);
    }
    y2.x = fmaxf(y2.x, 0.0f);
    y2.y = fmaxf(y2.y, 0.0f);

    // layer b
    float2 z2 = sbb[fl];
#pragma unroll
    for (int kp = 0; kp < 16; kp++) {
        float xx = __shfl_sync(0xffffffffu, y2.x, base + kp);
        float xy = __shfl_sync(0xffffffffu, y2.y, base + kp);
        float4 w = sWb[kp * 16 + fl];
        z2.x = fmaf(xx, w.x, z2.x);
        z2.x = fmaf(xy, w.y, z2.x);
        z2.y = fmaf(xx, w.z, z2.y);
        z2.y = fmaf(xy, w.w, z2.y);
    }
    z2.x = fmaxf(z2.x, 0.0f);   // >= 0 -> int atomicMax valid
    z2.y = fmaxf(z2.y, 0.0f);

    int g = graph_ids[n];
    atomicMax((int*)&g_pooled[g * 32 + 2 * fl],     __float_as_int(z2.x));
    atomicMax((int*)&g_pooled[g * 32 + 2 * fl + 1], __float_as_int(z2.y));
}

// ---------------- classifier head ----------------
__global__ void head_kernel(const float* __restrict__ Wm1, const float* __restrict__ bm1,
                            const float* __restrict__ Wm2, const float* __restrict__ bm2,
                            float* __restrict__ out) {
    int g = threadIdx.x;
    if (g >= NG) return;
    float p[32];
#pragma unroll
    for (int k = 0; k < 32; k++) p[k] = g_pooled[g * 32 + k];
    float hid[16];
#pragma unroll
    for (int jj = 0; jj < 16; jj++) {
        float a = bm1[jj];
#pragma unroll
        for (int k = 0; k < 32; k++) a = fmaf(p[k], Wm1[k * 16 + jj], a);
        hid[jj] = fmaxf(a, 0.0f);
    }
    float l0 = bm2[0], l1 = bm2[1];
#pragma unroll
    for (int jj = 0; jj < 16; jj++) {
        l0 = fmaf(hid[jj], Wm2[jj * 2 + 0], l0);
        l1 = fmaf(hid[jj], Wm2[jj * 2 + 1], l1);
    }
    float m = fmaxf(l0, l1);
    float e0 = expf(l0 - m);
    float e1 = expf(l1 - m);
    float inv = 1.0f / (e0 + e1);
    out[g * 2 + 0] = e0 * inv;
    out[g * 2 + 1] = e1 * inv;
}

extern "C" void kernel_launch(void* const* d_in, const int* in_sizes, int n_in,
                              void* d_out, int out_size) {
    const float* node_feat = (const float*)d_in[0];
    const float* edge_feat = (const float*)d_in[1];
    const int*   src       = (const int*)d_in[2];
    const int*   dst       = (const int*)d_in[3];
    const int*   graph_ids = (const int*)d_in[4];
    const float* W1a = (const float*)d_in[5];
    const float* b1a = (const float*)d_in[6];
    const float* W1b = (const float*)d_in[7];
    const float* b1b = (const float*)d_in[8];
    const float* W2a = (const float*)d_in[9];
    const float* b2a = (const float*)d_in[10];
    const float* W2b = (const float*)d_in[11];
    const float* b2b = (const float*)d_in[12];
    const float* Wm1 = (const float*)d_in[13];
    const float* bm1 = (const float*)d_in[14];
    const float* Wm2 = (const float*)d_in[15];
    const float* bm2 = (const float*)d_in[16];
    float* out = (float*)d_out;

    setup_kernel<<<(NN * 8 + 255) / 256, 256>>>(node_feat);
    sort_kernel<<<NB_SCAN, 256>>>((const int4*)src, (const int4*)dst,
                                  (const float4*)edge_feat);
    node1_kernel<<<NN / 8, 256>>>(W1a, b1a, W1b, b1b);
    node2_kernel<<<NN / 16, 256>>>(W2a, b2a, W2b, b2b, graph_ids);
    head_kernel<<<1, 64>>>(Wm1, bm1, Wm2, bm2, out);
}

// round 11
// speedup vs baseline: 1.2544x; 1.2544x over previous
#include <cuda_runtime.h>
#include <cuda_fp16.h>
#include <stdint.h>
#include <math.h>

#define NN 200000
#define NE 6400000
#define NG 64
#define NB_SCAN 782   // ceil(NN/256); all blocks resident

// ---- device scratch (static, no runtime allocation) ----
__device__ int    g_count[NN];        // in-degree
__device__ int    g_cursor[NN];       // scatter cursor
__device__ int    g_off[NN];          // CSR offsets (exclusive scan)
__device__ int    g_bsum[1024];       // scan block totals
__device__ int    g_sync[4];          // global sync counters
__device__ uint4  g_sorted[NE];       // {src, ef01(half2), ef23(half2), 0} sorted by dst
__device__ __half g_nfh[NN * 8];      // node_feat as half, padded to 8/row (16B)
__device__ __half g_h1h[NN * 32];     // layer-1 output (fp16, 12.8MB)
__device__ float  g_pooled[NG * 32];

// ---------------- setup ----------------
__global__ void setup_kernel(const float* __restrict__ node_feat) {
    int i = blockIdx.x * blockDim.x + threadIdx.x;
    if (i < NN * 8) {
        int n = i >> 3, k = i & 7;
        g_nfh[i] = __float2half_rn((k < 7) ? node_feat[n * 7 + k] : 0.0f);
    }
    if (i < NN) { g_count[i] = 0; g_cursor[i] = 0; }
    if (i < NG * 32) g_pooled[i] = 0.0f;
    if (i < 4) g_sync[i] = 0;
}

__device__ __forceinline__ unsigned int pack_h2(float a, float b) {
    __half2 h = __floats2half2_rn(a, b);
    return *(unsigned int*)&h;
}

__device__ __forceinline__ void gsync(int idx) {
    __syncthreads();
    __threadfence();
    if (threadIdx.x == 0) {
        atomicAdd(&g_sync[idx], 1);
        while (atomicAdd(&g_sync[idx], 0) < NB_SCAN) { }
    }
    __syncthreads();
}

// ---------------- persistent sort: hist -> scan -> scatter ----------------
__global__ void sort_kernel(const int4* __restrict__ src4,
                            const int4* __restrict__ dst4,
                            const float4* __restrict__ ef4) {
    __shared__ int s[256];
    int t = threadIdx.x;
    int b = blockIdx.x;
    int i = b * 256 + t;
    const int nquads = NE / 4;

    for (int q = b * 256 + t; q < nquads; q += NB_SCAN * 256) {
        int4 d = dst4[q];
        atomicAdd(&g_count[d.x], 1);
        atomicAdd(&g_count[d.y], 1);
        atomicAdd(&g_count[d.z], 1);
        atomicAdd(&g_count[d.w], 1);
    }
    gsync(0);

    int v = (i < NN) ? g_count[i] : 0;
    s[t] = v;
    __syncthreads();
    for (int off = 1; off < 256; off <<= 1) {
        int add = (t >= off) ? s[t - off] : 0;
        __syncthreads();
        s[t] += add;
        __syncthreads();
    }
    int local_excl = s[t] - v;
    if (t == 255) {
        g_bsum[b] = s[255];
        __threadfence();
        atomicAdd(&g_sync[1], 1);
    }
    if (t == 0) { while (atomicAdd(&g_sync[1], 0) < NB_SCAN) { } }
    __syncthreads();

    int pre = 0;
    for (int k = t; k < b; k += 256) pre += g_bsum[k];
    s[t] = pre;
    __syncthreads();
    for (int o = 128; o; o >>= 1) {
        if (t < o) s[t] += s[t + o];
        __syncthreads();
    }
    if (i < NN) g_off[i] = s[0] + local_excl;

    gsync(2);

    for (int q = b * 256 + t; q < nquads; q += NB_SCAN * 256) {
        int4 sv = src4[q];
        int4 dv = dst4[q];
        float4 e0 = ef4[q * 4 + 0];
        float4 e1 = ef4[q * 4 + 1];
        float4 e2 = ef4[q * 4 + 2];
        float4 e3 = ef4[q * 4 + 3];
        uint4 w;
        w.w = 0u;

        int p0 = g_off[dv.x] + atomicAdd(&g_cursor[dv.x], 1);
        w.x = (unsigned int)sv.x; w.y = pack_h2(e0.x, e0.y); w.z = pack_h2(e0.z, e0.w);
        g_sorted[p0] = w;
        int p1 = g_off[dv.y] + atomicAdd(&g_cursor[dv.y], 1);
        w.x = (unsigned int)sv.y; w.y = pack_h2(e1.x, e1.y); w.z = pack_h2(e1.z, e1.w);
        g_sorted[p1] = w;
        int p2 = g_off[dv.z] + atomicAdd(&g_cursor[dv.z], 1);
        w.x = (unsigned int)sv.z; w.y = pack_h2(e2.x, e2.y); w.z = pack_h2(e2.z, e2.w);
        g_sorted[p2] = w;
        int p3 = g_off[dv.w] + atomicAdd(&g_cursor[dv.w], 1);
        w.x = (unsigned int)sv.w; w.y = pack_h2(e3.x, e3.y); w.z = pack_h2(e3.z, e3.w);
        g_sorted[p3] = w;
    }
}

// ---------------- layer 1: edge stream + nf gather, smem-staged MLP layer b ----------------
__global__ void node1_kernel(const float* __restrict__ W1a, const float* __restrict__ b1a,
                             const float* __restrict__ W1b, const float* __restrict__ b1b) {
    __shared__ float  sW1a[11 * 32];
    __shared__ float4 sW1bT[256];   // [kq*32+lane] = {W1b[4kq+j][lane]}
    __shared__ float  sb1a[32];
    __shared__ float  sb1b[32];
    __shared__ float  sX[8][32];
    int tid = threadIdx.x;
    for (int k = tid; k < 11 * 32; k += blockDim.x) sW1a[k] = W1a[k];
    for (int idx = tid; idx < 256; idx += blockDim.x) {
        int kq = idx >> 5, ln = idx & 31;
        sW1bT[kq * 32 + ln] = make_float4(W1b[(4 * kq + 0) * 32 + ln],
                                          W1b[(4 * kq + 1) * 32 + ln],
                                          W1b[(4 * kq + 2) * 32 + ln],
                                          W1b[(4 * kq + 3) * 32 + ln]);
    }
    if (tid < 32) { sb1a[tid] = b1a[tid]; sb1b[tid] = b1b[tid]; }
    __syncthreads();

    int warp = tid >> 5;
    int lane = tid & 31;
    int n = blockIdx.x * 8 + warp;
    if (n >= NN) return;

    int start = g_off[n];
    int deg   = g_count[n];

    float acc[11];
#pragma unroll
    for (int k = 0; k < 11; k++) acc[k] = 0.0f;

    const uint4* nfq = (const uint4*)g_nfh;
    for (int j = lane; j < deg; j += 32) {
        uint4 p = __ldg(&g_sorted[start + j]);
        float2 e01 = __half22float2(*(__half2*)&p.y);
        float2 e23 = __half22float2(*(__half2*)&p.z);
        acc[0] += e01.x; acc[1] += e01.y; acc[2] += e23.x; acc[3] += e23.y;
        uint4 nf = __ldg(&nfq[p.x]);
        float2 f0 = __half22float2(*(__half2*)&nf.x);
        float2 f1 = __half22float2(*(__half2*)&nf.y);
        float2 f2 = __half22float2(*(__half2*)&nf.z);
        float2 f3 = __half22float2(*(__half2*)&nf.w);
        acc[4] += f0.x; acc[5] += f0.y;
        acc[6] += f1.x; acc[7] += f1.y;
        acc[8] += f2.x; acc[9] += f2.y;
        acc[10] += f3.x;
    }

#pragma unroll
    for (int off = 16; off; off >>= 1) {
#pragma unroll
        for (int k = 0; k < 11; k++)
            acc[k] += __shfl_xor_sync(0xffffffffu, acc[k], off);
    }

    float invd = 1.0f / fmaxf((float)deg, 1.0f);

    float y = sb1a[lane];
#pragma unroll
    for (int k = 0; k < 11; k++)
        y = fmaf(acc[k] * invd, sW1a[k * 32 + lane], y);
    y = fmaxf(y, 0.0f);

    // layer b via smem staging + float4 weights
    sX[warp][lane] = y;
    __syncwarp();
    float z = sb1b[lane];
#pragma unroll
    for (int kq = 0; kq < 8; kq++) {
        float4 xv = *(const float4*)&sX[warp][kq * 4];  // broadcast
        float4 w  = sW1bT[kq * 32 + lane];
        z = fmaf(xv.x, w.x, z);
        z = fmaf(xv.y, w.y, z);
        z = fmaf(xv.z, w.z, z);
        z = fmaf(xv.w, w.w, z);
    }
    z = fmaxf(z, 0.0f);

    g_h1h[n * 32 + lane] = __float2half_rn(z);
}

// ---------------- layer 2: 16 dual-edge loads in flight + smem-staged MLP ----------------
__global__ void node2_kernel(const float* __restrict__ W2a, const float* __restrict__ b2a,
                             const float* __restrict__ W2b, const float* __restrict__ b2b,
                             const int* __restrict__ graph_ids) {
    __shared__ float4 sWaT[256];    // [kq*32+lane] = {W2a[4kq+j][lane]}
    __shared__ float4 sWbT[256];
    __shared__ float  sb2a[32];
    __shared__ float  sb2b[32];
    __shared__ float  sX[8][32];
    int tid = threadIdx.x;
    for (int idx = tid; idx < 256; idx += blockDim.x) {
        int kq = idx >> 5, ln = idx & 31;
        sWaT[kq * 32 + ln] = make_float4(W2a[(4 * kq + 0) * 32 + ln],
                                         W2a[(4 * kq + 1) * 32 + ln],
                                         W2a[(4 * kq + 2) * 32 + ln],
                                         W2a[(4 * kq + 3) * 32 + ln]);
        sWbT[kq * 32 + ln] = make_float4(W2b[(4 * kq + 0) * 32 + ln],
                                         W2b[(4 * kq + 1) * 32 + ln],
                                         W2b[(4 * kq + 2) * 32 + ln],
                                         W2b[(4 * kq + 3) * 32 + ln]);
    }
    if (tid < 32) { sb2a[tid] = b2a[tid]; sb2b[tid] = b2b[tid]; }
    __syncthreads();

    int warp = tid >> 5;
    int lane = tid & 31;
    int n = blockIdx.x * 8 + warp;
    if (n >= NN) return;

    int start = g_off[n];
    int deg   = g_count[n];

    int half = lane >> 4;     // 0: even edges, 1: odd edges
    int fl   = lane & 15;     // feature-pair index
    const __half2* h1p = (const __half2*)g_h1h;
    const unsigned int* sortedx = (const unsigned int*)g_sorted;  // .x at stride 4 words

    float2 accp = make_float2(0.0f, 0.0f);
    int jb = 0;
    for (; jb + 32 <= deg; jb += 32) {
        // one strided load: lane j holds src of edge jb+j
        int myidx = (int)__ldg(&sortedx[(size_t)(start + jb + lane) * 4]);
        // 16 independent half2 loads, each covering 2 edges (even in lanes 0-15, odd in 16-31)
        float2 v[16];
#pragma unroll
        for (int p = 0; p < 16; p++) {
            int sE = __shfl_sync(0xffffffffu, myidx, 2 * p + half);
            v[p] = __half22float2(__ldg(&h1p[sE * 16 + fl]));
        }
#pragma unroll
        for (int p = 0; p < 16; p++) {
            accp.x += v[p].x;
            accp.y += v[p].y;
        }
    }
    // merge even/odd halves
    accp.x += __shfl_xor_sync(0xffffffffu, accp.x, 16);
    accp.y += __shfl_xor_sync(0xffffffffu, accp.y, 16);
    // redistribute: lane f takes component (f&1) of pair f>>1
    float xe = __shfl_sync(0xffffffffu, accp.x, lane >> 1);
    float xo = __shfl_sync(0xffffffffu, accp.y, lane >> 1);
    float x = (lane & 1) ? xo : xe;

    // tail (<32 edges), per-feature layout
    for (int j = jb; j < deg; j++) {
        int s = (int)g_sorted[start + j].x;   // uniform broadcast
        x += __half2float(__ldg(&g_h1h[s * 32 + lane]));
    }
    x /= fmaxf((float)deg, 1.0f);

    // MLP layer a (smem staging + float4 weights)
    sX[warp][lane] = x;
    __syncwarp();
    float y = sb2a[lane];
#pragma unroll
    for (int kq = 0; kq < 8; kq++) {
        float4 xv = *(const float4*)&sX[warp][kq * 4];
        float4 w  = sWaT[kq * 32 + lane];
        y = fmaf(xv.x, w.x, y);
        y = fmaf(xv.y, w.y, y);
        y = fmaf(xv.z, w.z, y);
        y = fmaf(xv.w, w.w, y);
    }
    y = fmaxf(y, 0.0f);

    // MLP layer b
    __syncwarp();
    sX[warp][lane] = y;
    __syncwarp();
    float z = sb2b[lane];
#pragma unroll
    for (int kq = 0; kq < 8; kq++) {
        float4 xv = *(const float4*)&sX[warp][kq * 4];
        float4 w  = sWbT[kq * 32 + lane];
        z = fmaf(xv.x, w.x, z);
        z = fmaf(xv.y, w.y, z);
        z = fmaf(xv.z, w.z, z);
        z = fmaf(xv.w, w.w, z);
    }
    z = fmaxf(z, 0.0f);  // >= 0 -> int-compare atomicMax is order-safe

    int g = graph_ids[n];
    atomicMax((int*)&g_pooled[g * 32 + lane], __float_as_int(z));
}

// ---------------- classifier head ----------------
__global__ void head_kernel(const float* __restrict__ Wm1, const float* __restrict__ bm1,
                            const float* __restrict__ Wm2, const float* __restrict__ bm2,
                            float* __restrict__ out) {
    int g = threadIdx.x;
    if (g >= NG) return;
    float p[32];
#pragma unroll
    for (int k = 0; k < 32; k++) p[k] = g_pooled[g * 32 + k];
    float hid[16];
#pragma unroll
    for (int jj = 0; jj < 16; jj++) {
        float a = bm1[jj];
#pragma unroll
        for (int k = 0; k < 32; k++) a = fmaf(p[k], Wm1[k * 16 + jj], a);
        hid[jj] = fmaxf(a, 0.0f);
    }
    float l0 = bm2[0], l1 = bm2[1];
#pragma unroll
    for (int jj = 0; jj < 16; jj++) {
        l0 = fmaf(hid[jj], Wm2[jj * 2 + 0], l0);
        l1 = fmaf(hid[jj], Wm2[jj * 2 + 1], l1);
    }
    float m = fmaxf(l0, l1);
    float e0 = expf(l0 - m);
    float e1 = expf(l1 - m);
    float inv = 1.0f / (e0 + e1);
    out[g * 2 + 0] = e0 * inv;
    out[g * 2 + 1] = e1 * inv;
}

extern "C" void kernel_launch(void* const* d_in, const int* in_sizes, int n_in,
                              void* d_out, int out_size) {
    const float* node_feat = (const float*)d_in[0];
    const float* edge_feat = (const float*)d_in[1];
    const int*   src       = (const int*)d_in[2];
    const int*   dst       = (const int*)d_in[3];
    const int*   graph_ids = (const int*)d_in[4];
    const float* W1a = (const float*)d_in[5];
    const float* b1a = (const float*)d_in[6];
    const float* W1b = (const float*)d_in[7];
    const float* b1b = (const float*)d_in[8];
    const float* W2a = (const float*)d_in[9];
    const float* b2a = (const float*)d_in[10];
    const float* W2b = (const float*)d_in[11];
    const float* b2b = (const float*)d_in[12];
    const float* Wm1 = (const float*)d_in[13];
    const float* bm1 = (const float*)d_in[14];
    const float* Wm2 = (const float*)d_in[15];
    const float* bm2 = (const float*)d_in[16];
    float* out = (float*)d_out;

    setup_kernel<<<(NN * 8 + 255) / 256, 256>>>(node_feat);
    sort_kernel<<<NB_SCAN, 256>>>((const int4*)src, (const int4*)dst,
                                  (const float4*)edge_feat);
    node1_kernel<<<NN / 8, 256>>>(W1a, b1a, W1b, b1b);
    node2_kernel<<<NN / 8, 256>>>(W2a, b2a, W2b, b2b, graph_ids);
    head_kernel<<<1, 64>>>(Wm1, bm1, Wm2, bm2, out);
}

// round 12
// speedup vs baseline: 1.3581x; 1.0827x over previous
#include <cuda_runtime.h>
#include <cuda_fp16.h>
#include <stdint.h>
#include <math.h>

#define NN 200000
#define NE 6400000
#define NG 64
#define NB_SCAN 782   // ceil(NN/256); all blocks resident

// ---- device scratch (static, no runtime allocation) ----
__device__ int    g_count[NN];        // in-degree
__device__ int    g_off[NN];          // CSR offsets (exclusive scan)
__device__ int    g_rank[NE];         // per-edge rank within its dst bucket
__device__ int    g_bsum[1024];       // scan block totals
__device__ int    g_sync[4];          // global sync counters
__device__ uint4  g_sorted[NE];       // {src, ef01(half2), ef23(half2), 0} sorted by dst
__device__ __half g_nfh[NN * 8];      // node_feat as half, padded to 8/row (16B)
__device__ __half g_h1h[NN * 32];     // layer-1 output (fp16, 12.8MB)
__device__ float  g_pooled[NG * 32];

// ---------------- setup ----------------
__global__ void setup_kernel(const float* __restrict__ node_feat) {
    int i = blockIdx.x * blockDim.x + threadIdx.x;
    if (i < NN * 8) {
        int n = i >> 3, k = i & 7;
        g_nfh[i] = __float2half_rn((k < 7) ? node_feat[n * 7 + k] : 0.0f);
    }
    if (i < NN) g_count[i] = 0;
    if (i < NG * 32) g_pooled[i] = 0.0f;
    if (i < 4) g_sync[i] = 0;
}

__device__ __forceinline__ unsigned int pack_h2(float a, float b) {
    __half2 h = __floats2half2_rn(a, b);
    return *(unsigned int*)&h;
}

__device__ __forceinline__ void gsync(int idx) {
    __syncthreads();
    __threadfence();
    if (threadIdx.x == 0) {
        atomicAdd(&g_sync[idx], 1);
        while (atomicAdd(&g_sync[idx], 0) < NB_SCAN) { }
    }
    __syncthreads();
}

// ---------------- persistent sort: hist(+rank) -> scan -> scatter (atomic-free) ----------------
__global__ void sort_kernel(const int4* __restrict__ src4,
                            const int4* __restrict__ dst4,
                            const float4* __restrict__ ef4) {
    __shared__ int s[256];
    int t = threadIdx.x;
    int b = blockIdx.x;
    int i = b * 256 + t;
    const int nquads = NE / 4;
    int4* rank4 = (int4*)g_rank;

    // --- phase 0: histogram; atomic return value = rank within bucket ---
    for (int q = b * 256 + t; q < nquads; q += NB_SCAN * 256) {
        int4 d = dst4[q];
        int4 r;
        r.x = atomicAdd(&g_count[d.x], 1);
        r.y = atomicAdd(&g_count[d.y], 1);
        r.z = atomicAdd(&g_count[d.z], 1);
        r.w = atomicAdd(&g_count[d.w], 1);
        rank4[q] = r;
    }
    gsync(0);

    // --- phase 1: block-local inclusive scan of degrees ---
    int v = (i < NN) ? g_count[i] : 0;
    s[t] = v;
    __syncthreads();
    for (int off = 1; off < 256; off <<= 1) {
        int add = (t >= off) ? s[t - off] : 0;
        __syncthreads();
        s[t] += add;
        __syncthreads();
    }
    int local_excl = s[t] - v;
    if (t == 255) {
        g_bsum[b] = s[255];
        __threadfence();
        atomicAdd(&g_sync[1], 1);
    }
    if (t == 0) { while (atomicAdd(&g_sync[1], 0) < NB_SCAN) { } }
    __syncthreads();

    // --- phase 2: block prefix from published totals ---
    int pre = 0;
    for (int k = t; k < b; k += 256) pre += g_bsum[k];
    s[t] = pre;
    __syncthreads();
    for (int o = 128; o; o >>= 1) {
        if (t < o) s[t] += s[t + o];
        __syncthreads();
    }
    if (i < NN) g_off[i] = s[0] + local_excl;

    gsync(2);

    // --- phase 3: scatter, NO atomics: pos = off[dst] + rank ---
    for (int q = b * 256 + t; q < nquads; q += NB_SCAN * 256) {
        int4 sv = src4[q];
        int4 dv = dst4[q];
        int4 rv = rank4[q];
        float4 e0 = ef4[q * 4 + 0];
        float4 e1 = ef4[q * 4 + 1];
        float4 e2 = ef4[q * 4 + 2];
        float4 e3 = ef4[q * 4 + 3];
        uint4 w;
        w.w = 0u;

        w.x = (unsigned int)sv.x; w.y = pack_h2(e0.x, e0.y); w.z = pack_h2(e0.z, e0.w);
        g_sorted[g_off[dv.x] + rv.x] = w;
        w.x = (unsigned int)sv.y; w.y = pack_h2(e1.x, e1.y); w.z = pack_h2(e1.z, e1.w);
        g_sorted[g_off[dv.y] + rv.y] = w;
        w.x = (unsigned int)sv.z; w.y = pack_h2(e2.x, e2.y); w.z = pack_h2(e2.z, e2.w);
        g_sorted[g_off[dv.z] + rv.z] = w;
        w.x = (unsigned int)sv.w; w.y = pack_h2(e3.x, e3.y); w.z = pack_h2(e3.z, e3.w);
        g_sorted[g_off[dv.w] + rv.w] = w;
    }
}

// ---------------- layer 1: edge stream + nf gather, smem-staged MLP layer b ----------------
__global__ void node1_kernel(const float* __restrict__ W1a, const float* __restrict__ b1a,
                             const float* __restrict__ W1b, const float* __restrict__ b1b) {
    __shared__ float  sW1a[11 * 32];
    __shared__ float4 sW1bT[256];   // [kq*32+lane] = {W1b[4kq+j][lane]}
    __shared__ float  sb1a[32];
    __shared__ float  sb1b[32];
    __shared__ float  sX[8][32];
    int tid = threadIdx.x;
    for (int k = tid; k < 11 * 32; k += blockDim.x) sW1a[k] = W1a[k];
    for (int idx = tid; idx < 256; idx += blockDim.x) {
        int kq = idx >> 5, ln = idx & 31;
        sW1bT[kq * 32 + ln] = make_float4(W1b[(4 * kq + 0) * 32 + ln],
                                          W1b[(4 * kq + 1) * 32 + ln],
                                          W1b[(4 * kq + 2) * 32 + ln],
                                          W1b[(4 * kq + 3) * 32 + ln]);
    }
    if (tid < 32) { sb1a[tid] = b1a[tid]; sb1b[tid] = b1b[tid]; }
    __syncthreads();

    int warp = tid >> 5;
    int lane = tid & 31;
    int n = blockIdx.x * 8 + warp;

    int start = g_off[n];
    int deg   = g_count[n];

    float acc[11];
#pragma unroll
    for (int k = 0; k < 11; k++) acc[k] = 0.0f;

    const uint4* nfq = (const uint4*)g_nfh;
    for (int j = lane; j < deg; j += 32) {
        uint4 p = __ldg(&g_sorted[start + j]);
        float2 e01 = __half22float2(*(__half2*)&p.y);
        float2 e23 = __half22float2(*(__half2*)&p.z);
        acc[0] += e01.x; acc[1] += e01.y; acc[2] += e23.x; acc[3] += e23.y;
        uint4 nf = __ldg(&nfq[p.x]);
        float2 f0 = __half22float2(*(__half2*)&nf.x);
        float2 f1 = __half22float2(*(__half2*)&nf.y);
        float2 f2 = __half22float2(*(__half2*)&nf.z);
        float2 f3 = __half22float2(*(__half2*)&nf.w);
        acc[4] += f0.x; acc[5] += f0.y;
        acc[6] += f1.x; acc[7] += f1.y;
        acc[8] += f2.x; acc[9] += f2.y;
        acc[10] += f3.x;
    }

#pragma unroll
    for (int off = 16; off; off >>= 1) {
#pragma unroll
        for (int k = 0; k < 11; k++)
            acc[k] += __shfl_xor_sync(0xffffffffu, acc[k], off);
    }

    float invd = 1.0f / fmaxf((float)deg, 1.0f);

    float y = sb1a[lane];
#pragma unroll
    for (int k = 0; k < 11; k++)
        y = fmaf(acc[k] * invd, sW1a[k * 32 + lane], y);
    y = fmaxf(y, 0.0f);

    // layer b via smem staging + float4 weights
    sX[warp][lane] = y;
    __syncwarp();
    float z = sb1b[lane];
#pragma unroll
    for (int kq = 0; kq < 8; kq++) {
        float4 xv = *(const float4*)&sX[warp][kq * 4];  // broadcast
        float4 w  = sW1bT[kq * 32 + lane];
        z = fmaf(xv.x, w.x, z);
        z = fmaf(xv.y, w.y, z);
        z = fmaf(xv.z, w.z, z);
        z = fmaf(xv.w, w.w, z);
    }
    z = fmaxf(z, 0.0f);

    g_h1h[n * 32 + lane] = __float2half_rn(z);
}

// ---------------- layer 2: R9 dual-half2 gather + smem-staged MLP + pool ----------------
__global__ void __launch_bounds__(256) node2_kernel(
        const float* __restrict__ W2a, const float* __restrict__ b2a,
        const float* __restrict__ W2b, const float* __restrict__ b2b,
        const int* __restrict__ graph_ids) {
    __shared__ float4 sWaT[256];    // [kq*32+lane] = {W2a[4kq+j][lane]}
    __shared__ float4 sWbT[256];
    __shared__ float  sb2a[32];
    __shared__ float  sb2b[32];
    __shared__ float  sX[8][32];
    int tid = threadIdx.x;
    for (int idx = tid; idx < 256; idx += blockDim.x) {
        int kq = idx >> 5, ln = idx & 31;
        sWaT[kq * 32 + ln] = make_float4(W2a[(4 * kq + 0) * 32 + ln],
                                         W2a[(4 * kq + 1) * 32 + ln],
                                         W2a[(4 * kq + 2) * 32 + ln],
                                         W2a[(4 * kq + 3) * 32 + ln]);
        sWbT[kq * 32 + ln] = make_float4(W2b[(4 * kq + 0) * 32 + ln],
                                         W2b[(4 * kq + 1) * 32 + ln],
                                         W2b[(4 * kq + 2) * 32 + ln],
                                         W2b[(4 * kq + 3) * 32 + ln]);
    }
    if (tid < 32) { sb2a[tid] = b2a[tid]; sb2b[tid] = b2b[tid]; }
    __syncthreads();

    int warp = tid >> 5;
    int lane = tid & 31;
    int n = blockIdx.x * 8 + warp;

    int start = g_off[n];
    int deg   = g_count[n];

    int half = lane >> 4;     // 0: even edges, 1: odd edges
    int fl   = lane & 15;     // feature-pair index
    const __half2* h1p = (const __half2*)g_h1h;

    float2 a0 = make_float2(0.f, 0.f);
    float2 a1 = make_float2(0.f, 0.f);
    float2 a2 = make_float2(0.f, 0.f);
    float2 a3 = make_float2(0.f, 0.f);

    int j = 0;
    for (; j + 16 <= deg; j += 16) {
        int idx = 0;
        if (lane < 16) idx = (int)g_sorted[start + j + lane].x;
        int r0 = __shfl_sync(0xffffffffu, idx,  0 + half);
        int r1 = __shfl_sync(0xffffffffu, idx,  2 + half);
        int r2 = __shfl_sync(0xffffffffu, idx,  4 + half);
        int r3 = __shfl_sync(0xffffffffu, idx,  6 + half);
        int r4 = __shfl_sync(0xffffffffu, idx,  8 + half);
        int r5 = __shfl_sync(0xffffffffu, idx, 10 + half);
        int r6 = __shfl_sync(0xffffffffu, idx, 12 + half);
        int r7 = __shfl_sync(0xffffffffu, idx, 14 + half);
        float2 v0 = __half22float2(__ldg(&h1p[r0 * 16 + fl]));
        float2 v1 = __half22float2(__ldg(&h1p[r1 * 16 + fl]));
        float2 v2 = __half22float2(__ldg(&h1p[r2 * 16 + fl]));
        float2 v3 = __half22float2(__ldg(&h1p[r3 * 16 + fl]));
        float2 v4 = __half22float2(__ldg(&h1p[r4 * 16 + fl]));
        float2 v5 = __half22float2(__ldg(&h1p[r5 * 16 + fl]));
        float2 v6 = __half22float2(__ldg(&h1p[r6 * 16 + fl]));
        float2 v7 = __half22float2(__ldg(&h1p[r7 * 16 + fl]));
        a0.x += v0.x + v4.x; a0.y += v0.y + v4.y;
        a1.x += v1.x + v5.x; a1.y += v1.y + v5.y;
        a2.x += v2.x + v6.x; a2.y += v2.y + v6.y;
        a3.x += v3.x + v7.x; a3.y += v3.y + v7.y;
    }

    float2 accp;
    accp.x = (a0.x + a1.x) + (a2.x + a3.x);
    accp.y = (a0.y + a1.y) + (a2.y + a3.y);
    accp.x += __shfl_xor_sync(0xffffffffu, accp.x, 16);
    accp.y += __shfl_xor_sync(0xffffffffu, accp.y, 16);
    float xe = __shfl_sync(0xffffffffu, accp.x, lane >> 1);
    float xo = __shfl_sync(0xffffffffu, accp.y, lane >> 1);
    float x = (lane & 1) ? xo : xe;

    // tail (< 16 edges), per-feature layout
    for (; j < deg; j++) {
        int s = (int)g_sorted[start + j].x;   // uniform broadcast
        x += __half2float(__ldg(&g_h1h[s * 32 + lane]));
    }
    x /= fmaxf((float)deg, 1.0f);

    // MLP layer a (smem staging + float4 weights)
    sX[warp][lane] = x;
    __syncwarp();
    float y = sb2a[lane];
#pragma unroll
    for (int kq = 0; kq < 8; kq++) {
        float4 xv = *(const float4*)&sX[warp][kq * 4];
        float4 w  = sWaT[kq * 32 + lane];
        y = fmaf(xv.x, w.x, y);
        y = fmaf(xv.y, w.y, y);
        y = fmaf(xv.z, w.z, y);
        y = fmaf(xv.w, w.w, y);
    }
    y = fmaxf(y, 0.0f);

    // MLP layer b
    __syncwarp();
    sX[warp][lane] = y;
    __syncwarp();
    float z = sb2b[lane];
#pragma unroll
    for (int kq = 0; kq < 8; kq++) {
        float4 xv = *(const float4*)&sX[warp][kq * 4];
        float4 w  = sWbT[kq * 32 + lane];
        z = fmaf(xv.x, w.x, z);
        z = fmaf(xv.y, w.y, z);
        z = fmaf(xv.z, w.z, z);
        z = fmaf(xv.w, w.w, z);
    }
    z = fmaxf(z, 0.0f);  // >= 0 -> int-compare atomicMax is order-safe

    int g = graph_ids[n];
    atomicMax((int*)&g_pooled[g * 32 + lane], __float_as_int(z));
}

// ---------------- classifier head ----------------
__global__ void head_kernel(const float* __restrict__ Wm1, const float* __restrict__ bm1,
                            const float* __restrict__ Wm2, const float* __restrict__ bm2,
                            float* __restrict__ out) {
    int g = threadIdx.x;
    if (g >= NG) return;
    float p[32];
#pragma unroll
    for (int k = 0; k < 32; k++) p[k] = g_pooled[g * 32 + k];
    float hid[16];
#pragma unroll
    for (int jj = 0; jj < 16; jj++) {
        float a = bm1[jj];
#pragma unroll
        for (int k = 0; k < 32; k++) a = fmaf(p[k], Wm1[k * 16 + jj], a);
        hid[jj] = fmaxf(a, 0.0f);
    }
    float l0 = bm2[0], l1 = bm2[1];
#pragma unroll
    for (int jj = 0; jj < 16; jj++) {
        l0 = fmaf(hid[jj], Wm2[jj * 2 + 0], l0);
        l1 = fmaf(hid[jj], Wm2[jj * 2 + 1], l1);
    }
    float m = fmaxf(l0, l1);
    float e0 = expf(l0 - m);
    float e1 = expf(l1 - m);
    float inv = 1.0f / (e0 + e1);
    out[g * 2 + 0] = e0 * inv;
    out[g * 2 + 1] = e1 * inv;
}

extern "C" void kernel_launch(void* const* d_in, const int* in_sizes, int n_in,
                              void* d_out, int out_size) {
    const float* node_feat = (const float*)d_in[0];
    const float* edge_feat = (const float*)d_in[1];
    const int*   src       = (const int*)d_in[2];
    const int*   dst       = (const int*)d_in[3];
    const int*   graph_ids = (const int*)d_in[4];
    const float* W1a = (const float*)d_in[5];
    const float* b1a = (const float*)d_in[6];
    const float* W1b = (const float*)d_in[7];
    const float* b1b = (const float*)d_in[8];
    const float* W2a = (const float*)d_in[9];
    const float* b2a = (const float*)d_in[10];
    const float* W2b = (const float*)d_in[11];
    const float* b2b = (const float*)d_in[12];
    const float* Wm1 = (const float*)d_in[13];
    const float* bm1 = (const float*)d_in[14];
    const float* Wm2 = (const float*)d_in[15];
    const float* bm2 = (const float*)d_in[16];
    float* out = (float*)d_out;

    setup_kernel<<<(NN * 8 + 255) / 256, 256>>>(node_feat);
    sort_kernel<<<NB_SCAN, 256>>>((const int4*)src, (const int4*)dst,
                                  (const float4*)edge_feat);
    node1_kernel<<<NN / 8, 256>>>(W1a, b1a, W1b, b1b);
    node2_kernel<<<NN / 8, 256>>>(W2a, b2a, W2b, b2b, graph_ids);
    head_kernel<<<1, 64>>>(Wm1, bm1, Wm2, bm2, out);
}

// round 13
// speedup vs baseline: 1.3673x; 1.0068x over previous
#include <cuda_runtime.h>
#include <cuda_fp16.h>
#include <stdint.h>
#include <math.h>

#define NN 200000
#define NE 6400000
#define NG 64
#define NB_SCAN 782   // ceil(NN/256); all blocks resident

// ---- device scratch (static, no runtime allocation) ----
__device__ int    g_count[NN];        // in-degree
__device__ int    g_off[NN];          // CSR offsets (exclusive scan)
__device__ int    g_rank[NE];         // per-edge rank within its dst bucket
__device__ int    g_bsum[1024];       // scan block totals
__device__ int    g_sync[4];          // global sync counters
__device__ uint4  g_sorted[NE];       // {src, ef01(half2), ef23(half2), 0} sorted by dst
__device__ __half g_nfh[NN * 8];      // node_feat as half, padded to 8/row (16B)
__device__ __half g_h1h[NN * 32];     // layer-1 output (fp16, 12.8MB)
__device__ float  g_pooled[NG * 32];

// ---------------- setup ----------------
__global__ void setup_kernel(const float* __restrict__ node_feat) {
    int i = blockIdx.x * blockDim.x + threadIdx.x;
    if (i < NN * 8) {
        int n = i >> 3, k = i & 7;
        g_nfh[i] = __float2half_rn((k < 7) ? node_feat[n * 7 + k] : 0.0f);
    }
    if (i < NN) g_count[i] = 0;
    if (i < NG * 32) g_pooled[i] = 0.0f;
    if (i < 4) g_sync[i] = 0;
}

__device__ __forceinline__ unsigned int pack_h2(float a, float b) {
    __half2 h = __floats2half2_rn(a, b);
    return *(unsigned int*)&h;
}

__device__ __forceinline__ void gsync(int idx) {
    __syncthreads();
    __threadfence();
    if (threadIdx.x == 0) {
        atomicAdd(&g_sync[idx], 1);
        while (atomicAdd(&g_sync[idx], 0) < NB_SCAN) { }
    }
    __syncthreads();
}

// ---------------- persistent sort: hist(+rank) -> scan -> atomic-free scatter ----------------
__global__ void sort_kernel(const int4* __restrict__ src4,
                            const int4* __restrict__ dst4,
                            const float4* __restrict__ ef4) {
    __shared__ int s[256];
    int t = threadIdx.x;
    int b = blockIdx.x;
    int i = b * 256 + t;
    const int nquads = NE / 4;
    int4* rank4 = (int4*)g_rank;

    // --- phase 0: histogram; atomic return value = rank within bucket ---
    for (int q = b * 256 + t; q < nquads; q += NB_SCAN * 256) {
        int4 d = dst4[q];
        int4 r;
        r.x = atomicAdd(&g_count[d.x], 1);
        r.y = atomicAdd(&g_count[d.y], 1);
        r.z = atomicAdd(&g_count[d.z], 1);
        r.w = atomicAdd(&g_count[d.w], 1);
        rank4[q] = r;
    }
    gsync(0);

    // --- phase 1: block-local inclusive scan of degrees ---
    int v = (i < NN) ? g_count[i] : 0;
    s[t] = v;
    __syncthreads();
    for (int off = 1; off < 256; off <<= 1) {
        int add = (t >= off) ? s[t - off] : 0;
        __syncthreads();
        s[t] += add;
        __syncthreads();
    }
    int local_excl = s[t] - v;
    if (t == 255) {
        g_bsum[b] = s[255];
        __threadfence();
        atomicAdd(&g_sync[1], 1);
    }
    if (t == 0) { while (atomicAdd(&g_sync[1], 0) < NB_SCAN) { } }
    __syncthreads();

    // --- phase 2: block prefix from published totals ---
    int pre = 0;
    for (int k = t; k < b; k += 256) pre += g_bsum[k];
    s[t] = pre;
    __syncthreads();
    for (int o = 128; o; o >>= 1) {
        if (t < o) s[t] += s[t + o];
        __syncthreads();
    }
    if (i < NN) g_off[i] = s[0] + local_excl;

    gsync(2);

    // --- phase 3: scatter, NO atomics: pos = off[dst] + rank ---
    for (int q = b * 256 + t; q < nquads; q += NB_SCAN * 256) {
        int4 sv = src4[q];
        int4 dv = dst4[q];
        int4 rv = rank4[q];
        float4 e0 = ef4[q * 4 + 0];
        float4 e1 = ef4[q * 4 + 1];
        float4 e2 = ef4[q * 4 + 2];
        float4 e3 = ef4[q * 4 + 3];
        uint4 w;
        w.w = 0u;

        w.x = (unsigned int)sv.x; w.y = pack_h2(e0.x, e0.y); w.z = pack_h2(e0.z, e0.w);
        g_sorted[g_off[dv.x] + rv.x] = w;
        w.x = (unsigned int)sv.y; w.y = pack_h2(e1.x, e1.y); w.z = pack_h2(e1.z, e1.w);
        g_sorted[g_off[dv.y] + rv.y] = w;
        w.x = (unsigned int)sv.z; w.y = pack_h2(e2.x, e2.y); w.z = pack_h2(e2.z, e2.w);
        g_sorted[g_off[dv.z] + rv.z] = w;
        w.x = (unsigned int)sv.w; w.y = pack_h2(e3.x, e3.y); w.z = pack_h2(e3.z, e3.w);
        g_sorted[g_off[dv.w] + rv.w] = w;
    }
}

// ---------------- layer 1 (R8 form): edge stream + one fp16 nf gather, shfl MLP ----------------
__global__ void node1_kernel(const float* __restrict__ W1a, const float* __restrict__ b1a,
                             const float* __restrict__ W1b, const float* __restrict__ b1b) {
    __shared__ float sW1a[11 * 32];
    __shared__ float sW1b[32 * 32];
    __shared__ float sb1a[32];
    __shared__ float sb1b[32];
    int tid = threadIdx.x;
    for (int k = tid; k < 11 * 32; k += blockDim.x) sW1a[k] = W1a[k];
    for (int k = tid; k < 32 * 32; k += blockDim.x) sW1b[k] = W1b[k];
    if (tid < 32) { sb1a[tid] = b1a[tid]; sb1b[tid] = b1b[tid]; }
    __syncthreads();

    int warp = tid >> 5;
    int lane = tid & 31;
    int n = blockIdx.x * 8 + warp;

    int start = g_off[n];
    int deg   = g_count[n];

    float acc[11];
#pragma unroll
    for (int k = 0; k < 11; k++) acc[k] = 0.0f;

    const uint4* nfq = (const uint4*)g_nfh;
    for (int j = lane; j < deg; j += 32) {
        uint4 p = __ldg(&g_sorted[start + j]);   // coalesced 16B stream
        float2 e01 = __half22float2(*(__half2*)&p.y);
        float2 e23 = __half22float2(*(__half2*)&p.z);
        acc[0] += e01.x; acc[1] += e01.y; acc[2] += e23.x; acc[3] += e23.y;
        uint4 nf = __ldg(&nfq[p.x]);             // ONE 16B gather (L2-resident)
        float2 f0 = __half22float2(*(__half2*)&nf.x);
        float2 f1 = __half22float2(*(__half2*)&nf.y);
        float2 f2 = __half22float2(*(__half2*)&nf.z);
        float2 f3 = __half22float2(*(__half2*)&nf.w);
        acc[4] += f0.x; acc[5] += f0.y;
        acc[6] += f1.x; acc[7] += f1.y;
        acc[8] += f2.x; acc[9] += f2.y;
        acc[10] += f3.x;
    }

#pragma unroll
    for (int off = 16; off; off >>= 1) {
#pragma unroll
        for (int k = 0; k < 11; k++)
            acc[k] += __shfl_xor_sync(0xffffffffu, acc[k], off);
    }

    float invd = 1.0f / fmaxf((float)deg, 1.0f);

    float y = sb1a[lane];
#pragma unroll
    for (int k = 0; k < 11; k++)
        y = fmaf(acc[k] * invd, sW1a[k * 32 + lane], y);
    y = fmaxf(y, 0.0f);

    float z = sb1b[lane];
#pragma unroll
    for (int k = 0; k < 32; k++) {
        float yk = __shfl_sync(0xffffffffu, y, k);
        z = fmaf(yk, sW1b[k * 32 + lane], z);
    }
    z = fmaxf(z, 0.0f);

    g_h1h[n * 32 + lane] = __float2half_rn(z);
}

// ---------------- layer 2 (R9 + pipelined idx prefetch + occupancy bound) ----------------
__global__ void __launch_bounds__(256, 6) node2_kernel(
        const float* __restrict__ W2a, const float* __restrict__ b2a,
        const float* __restrict__ W2b, const float* __restrict__ b2b,
        const int* __restrict__ graph_ids) {
    __shared__ float sW2a[32 * 32];
    __shared__ float sW2b[32 * 32];
    __shared__ float sb2a[32];
    __shared__ float sb2b[32];
    int tid = threadIdx.x;
    for (int k = tid; k < 32 * 32; k += blockDim.x) { sW2a[k] = W2a[k]; sW2b[k] = W2b[k]; }
    if (tid < 32) { sb2a[tid] = b2a[tid]; sb2b[tid] = b2b[tid]; }
    __syncthreads();

    int warp = tid >> 5;
    int lane = tid & 31;
    int n = blockIdx.x * 8 + warp;

    int start = g_off[n];
    int deg   = g_count[n];

    int half = lane >> 4;     // 0: even edges, 1: odd edges
    int fl   = lane & 15;     // feature-pair index
    const __half2* h1p = (const __half2*)g_h1h;

    float2 a0 = make_float2(0.f, 0.f);
    float2 a1 = make_float2(0.f, 0.f);
    float2 a2 = make_float2(0.f, 0.f);
    float2 a3 = make_float2(0.f, 0.f);

    // software-pipelined: prefetch round r+1's indices while gathering round r
    int j = 0;
    int idx = 0;
    if (lane < 16 && 16 <= deg) idx = (int)g_sorted[start + lane].x;
    for (; j + 16 <= deg; j += 16) {
        int r0 = __shfl_sync(0xffffffffu, idx,  0 + half);
        int r1 = __shfl_sync(0xffffffffu, idx,  2 + half);
        int r2 = __shfl_sync(0xffffffffu, idx,  4 + half);
        int r3 = __shfl_sync(0xffffffffu, idx,  6 + half);
        int r4 = __shfl_sync(0xffffffffu, idx,  8 + half);
        int r5 = __shfl_sync(0xffffffffu, idx, 10 + half);
        int r6 = __shfl_sync(0xffffffffu, idx, 12 + half);
        int r7 = __shfl_sync(0xffffffffu, idx, 14 + half);
        int nidx = 0;
        if (lane < 16 && j + 32 <= deg)
            nidx = (int)g_sorted[start + j + 16 + lane].x;   // prefetch next round
        float2 v0 = __half22float2(__ldg(&h1p[r0 * 16 + fl]));
        float2 v1 = __half22float2(__ldg(&h1p[r1 * 16 + fl]));
        float2 v2 = __half22float2(__ldg(&h1p[r2 * 16 + fl]));
        float2 v3 = __half22float2(__ldg(&h1p[r3 * 16 + fl]));
        float2 v4 = __half22float2(__ldg(&h1p[r4 * 16 + fl]));
        float2 v5 = __half22float2(__ldg(&h1p[r5 * 16 + fl]));
        float2 v6 = __half22float2(__ldg(&h1p[r6 * 16 + fl]));
        float2 v7 = __half22float2(__ldg(&h1p[r7 * 16 + fl]));
        a0.x += v0.x + v4.x; a0.y += v0.y + v4.y;
        a1.x += v1.x + v5.x; a1.y += v1.y + v5.y;
        a2.x += v2.x + v6.x; a2.y += v2.y + v6.y;
        a3.x += v3.x + v7.x; a3.y += v3.y + v7.y;
        idx = nidx;
    }

    float2 accp;
    accp.x = (a0.x + a1.x) + (a2.x + a3.x);
    accp.y = (a0.y + a1.y) + (a2.y + a3.y);
    accp.x += __shfl_xor_sync(0xffffffffu, accp.x, 16);
    accp.y += __shfl_xor_sync(0xffffffffu, accp.y, 16);
    float xe = __shfl_sync(0xffffffffu, accp.x, lane >> 1);
    float xo = __shfl_sync(0xffffffffu, accp.y, lane >> 1);
    float x = (lane & 1) ? xo : xe;

    // tail (< 16 edges), per-feature layout
    for (; j < deg; j++) {
        int s = (int)g_sorted[start + j].x;   // uniform broadcast
        x += __half2float(__ldg(&g_h1h[s * 32 + lane]));
    }
    x /= fmaxf((float)deg, 1.0f);

    float y = sb2a[lane];
#pragma unroll
    for (int k = 0; k < 32; k++) {
        float xk = __shfl_sync(0xffffffffu, x, k);
        y = fmaf(xk, sW2a[k * 32 + lane], y);
    }
    y = fmaxf(y, 0.0f);

    float z = sb2b[lane];
#pragma unroll
    for (int k = 0; k < 32; k++) {
        float yk = __shfl_sync(0xffffffffu, y, k);
        z = fmaf(yk, sW2b[k * 32 + lane], z);
    }
    z = fmaxf(z, 0.0f);  // >= 0 -> int-compare atomicMax is order-safe

    int g = graph_ids[n];
    atomicMax((int*)&g_pooled[g * 32 + lane], __float_as_int(z));
}

// ---------------- classifier head ----------------
__global__ void head_kernel(const float* __restrict__ Wm1, const float* __restrict__ bm1,
                            const float* __restrict__ Wm2, const float* __restrict__ bm2,
                            float* __restrict__ out) {
    int g = threadIdx.x;
    if (g >= NG) return;
    float p[32];
#pragma unroll
    for (int k = 0; k < 32; k++) p[k] = g_pooled[g * 32 + k];
    float hid[16];
#pragma unroll
    for (int jj = 0; jj < 16; jj++) {
        float a = bm1[jj];
#pragma unroll
        for (int k = 0; k < 32; k++) a = fmaf(p[k], Wm1[k * 16 + jj], a);
        hid[jj] = fmaxf(a, 0.0f);
    }
    float l0 = bm2[0], l1 = bm2[1];
#pragma unroll
    for (int jj = 0; jj < 16; jj++) {
        l0 = fmaf(hid[jj], Wm2[jj * 2 + 0], l0);
        l1 = fmaf(hid[jj], Wm2[jj * 2 + 1], l1);
    }
    float m = fmaxf(l0, l1);
    float e0 = expf(l0 - m);
    float e1 = expf(l1 - m);
    float inv = 1.0f / (e0 + e1);
    out[g * 2 + 0] = e0 * inv;
    out[g * 2 + 1] = e1 * inv;
}

extern "C" void kernel_launch(void* const* d_in, const int* in_sizes, int n_in,
                              void* d_out, int out_size) {
    const float* node_feat = (const float*)d_in[0];
    const float* edge_feat = (const float*)d_in[1];
    const int*   src       = (const int*)d_in[2];
    const int*   dst       = (const int*)d_in[3];
    const int*   graph_ids = (const int*)d_in[4];
    const float* W1a = (const float*)d_in[5];
    const float* b1a = (const float*)d_in[6];
    const float* W1b = (const float*)d_in[7];
    const float* b1b = (const float*)d_in[8];
    const float* W2a = (const float*)d_in[9];
    const float* b2a = (const float*)d_in[10];
    const float* W2b = (const float*)d_in[11];
    const float* b2b = (const float*)d_in[12];
    const float* Wm1 = (const float*)d_in[13];
    const float* bm1 = (const float*)d_in[14];
    const float* Wm2 = (const float*)d_in[15];
    const float* bm2 = (const float*)d_in[16];
    float* out = (float*)d_out;

    setup_kernel<<<(NN * 8 + 255) / 256, 256>>>(node_feat);
    sort_kernel<<<NB_SCAN, 256>>>((const int4*)src, (const int4*)dst,
                                  (const float4*)edge_feat);
    node1_kernel<<<NN / 8, 256>>>(W1a, b1a, W1b, b1b);
    node2_kernel<<<NN / 8, 256>>>(W2a, b2a, W2b, b2b, graph_ids);
    head_kernel<<<1, 64>>>(Wm1, bm1, Wm2, bm2, out);
}

// round 14
// speedup vs baseline: 1.3807x; 1.0098x over previous
#include <cuda_runtime.h>
#include <cuda_fp16.h>
#include <stdint.h>
#include <math.h>

#define NN 200000
#define NE 6400000
#define NEP (NE + NN * 16)   // padded sorted-edge capacity
#define NG 64
#define NB_SCAN 782          // ceil(NN/256); all blocks resident

// ---- device scratch (static, no runtime allocation) ----
__device__ int    g_count[NN];          // in-degree
__device__ int    g_off[NN];            // padded CSR offsets
__device__ int    g_rank[NE];           // per-edge rank within its dst bucket
__device__ int    g_bsum[1024];         // scan block totals
__device__ int    g_sync[4];            // global sync counters
__device__ uint4  g_sorted[NEP];        // {src, ef01(half2), ef23(half2), 0} sorted by dst (+dummies)
__device__ __half g_nfh[NN * 8];        // node_feat as half, padded to 8/row (16B)
__device__ __half g_h1h[(NN + 1) * 32]; // layer-1 output (fp16); row NN = zeros (dummy target)
__device__ float  g_pooled[NG * 32];

// ---------------- setup ----------------
__global__ void setup_kernel(const float* __restrict__ node_feat) {
    int i = blockIdx.x * blockDim.x + threadIdx.x;
    if (i < NN * 8) {
        int n = i >> 3, k = i & 7;
        g_nfh[i] = __float2half_rn((k < 7) ? node_feat[n * 7 + k] : 0.0f);
    }
    if (i < NN) g_count[i] = 0;
    if (i < NG * 32) g_pooled[i] = 0.0f;
    if (i < 32) g_h1h[NN * 32 + i] = __float2half_rn(0.0f);  // dummy row
    if (i < 4) g_sync[i] = 0;
}

__device__ __forceinline__ unsigned int pack_h2(float a, float b) {
    __half2 h = __floats2half2_rn(a, b);
    return *(unsigned int*)&h;
}

__device__ __forceinline__ void gsync(int idx) {
    __syncthreads();
    __threadfence();
    if (threadIdx.x == 0) {
        atomicAdd(&g_sync[idx], 1);
        while (atomicAdd(&g_sync[idx], 0) < NB_SCAN) { }
    }
    __syncthreads();
}

// ---------------- persistent sort: hist(+rank) -> padded scan -> atomic-free scatter ----------------
__global__ void sort_kernel(const int4* __restrict__ src4,
                            const int4* __restrict__ dst4,
                            const float4* __restrict__ ef4) {
    __shared__ int s[256];
    int t = threadIdx.x;
    int b = blockIdx.x;
    int i = b * 256 + t;
    const int nquads = NE / 4;
    int4* rank4 = (int4*)g_rank;

    // --- phase 0: histogram; atomic return value = rank within bucket ---
    for (int q = b * 256 + t; q < nquads; q += NB_SCAN * 256) {
        int4 d = dst4[q];
        int4 r;
        r.x = atomicAdd(&g_count[d.x], 1);
        r.y = atomicAdd(&g_count[d.y], 1);
        r.z = atomicAdd(&g_count[d.z], 1);
        r.w = atomicAdd(&g_count[d.w], 1);
        rank4[q] = r;
    }
    gsync(0);

    // --- phase 1: block-local inclusive scan of PADDED degrees ---
    int deg_i = (i < NN) ? g_count[i] : 0;
    int v = (deg_i + 15) & ~15;           // padded to multiple of 16
    s[t] = v;
    __syncthreads();
    for (int off = 1; off < 256; off <<= 1) {
        int add = (t >= off) ? s[t - off] : 0;
        __syncthreads();
        s[t] += add;
        __syncthreads();
    }
    int local_excl = s[t] - v;
    if (t == 255) {
        g_bsum[b] = s[255];
        __threadfence();
        atomicAdd(&g_sync[1], 1);
    }
    if (t == 0) { while (atomicAdd(&g_sync[1], 0) < NB_SCAN) { } }
    __syncthreads();

    // --- phase 2: block prefix from published totals ---
    int pre = 0;
    for (int k = t; k < b; k += 256) pre += g_bsum[k];
    s[t] = pre;
    __syncthreads();
    for (int o = 128; o; o >>= 1) {
        if (t < o) s[t] += s[t + o];
        __syncthreads();
    }
    int my_off = s[0] + local_excl;
    if (i < NN) g_off[i] = my_off;

    // --- dummy fill for my node's pad region ---
    if (i < NN) {
        uint4 dummy;
        dummy.x = (unsigned int)NN; dummy.y = 0u; dummy.z = 0u; dummy.w = 0u;
        for (int k = deg_i; k < v; k++) g_sorted[my_off + k] = dummy;
    }

    gsync(2);

    // --- phase 3: scatter, NO atomics: pos = off[dst] + rank ---
    for (int q = b * 256 + t; q < nquads; q += NB_SCAN * 256) {
        int4 sv = src4[q];
        int4 dv = dst4[q];
        int4 rv = rank4[q];
        float4 e0 = ef4[q * 4 + 0];
        float4 e1 = ef4[q * 4 + 1];
        float4 e2 = ef4[q * 4 + 2];
        float4 e3 = ef4[q * 4 + 3];
        uint4 w;
        w.w = 0u;

        w.x = (unsigned int)sv.x; w.y = pack_h2(e0.x, e0.y); w.z = pack_h2(e0.z, e0.w);
        g_sorted[g_off[dv.x] + rv.x] = w;
        w.x = (unsigned int)sv.y; w.y = pack_h2(e1.x, e1.y); w.z = pack_h2(e1.z, e1.w);
        g_sorted[g_off[dv.y] + rv.y] = w;
        w.x = (unsigned int)sv.z; w.y = pack_h2(e2.x, e2.y); w.z = pack_h2(e2.z, e2.w);
        g_sorted[g_off[dv.z] + rv.z] = w;
        w.x = (unsigned int)sv.w; w.y = pack_h2(e3.x, e3.y); w.z = pack_h2(e3.z, e3.w);
        g_sorted[g_off[dv.w] + rv.w] = w;
    }
}

// ---------------- layer 1 (R8 proven form): edge stream + one fp16 nf gather ----------------
__global__ void node1_kernel(const float* __restrict__ W1a, const float* __restrict__ b1a,
                             const float* __restrict__ W1b, const float* __restrict__ b1b) {
    __shared__ float sW1a[11 * 32];
    __shared__ float sW1b[32 * 32];
    __shared__ float sb1a[32];
    __shared__ float sb1b[32];
    int tid = threadIdx.x;
    for (int k = tid; k < 11 * 32; k += blockDim.x) sW1a[k] = W1a[k];
    for (int k = tid; k < 32 * 32; k += blockDim.x) sW1b[k] = W1b[k];
    if (tid < 32) { sb1a[tid] = b1a[tid]; sb1b[tid] = b1b[tid]; }
    __syncthreads();

    int warp = tid >> 5;
    int lane = tid & 31;
    int n = blockIdx.x * 8 + warp;

    int start = g_off[n];
    int deg   = g_count[n];

    float acc[11];
#pragma unroll
    for (int k = 0; k < 11; k++) acc[k] = 0.0f;

    const uint4* nfq = (const uint4*)g_nfh;
    for (int j = lane; j < deg; j += 32) {
        uint4 p = __ldg(&g_sorted[start + j]);   // coalesced 16B stream
        float2 e01 = __half22float2(*(__half2*)&p.y);
        float2 e23 = __half22float2(*(__half2*)&p.z);
        acc[0] += e01.x; acc[1] += e01.y; acc[2] += e23.x; acc[3] += e23.y;
        uint4 nf = __ldg(&nfq[p.x]);             // ONE 16B gather (L2-resident)
        float2 f0 = __half22float2(*(__half2*)&nf.x);
        float2 f1 = __half22float2(*(__half2*)&nf.y);
        float2 f2 = __half22float2(*(__half2*)&nf.z);
        float2 f3 = __half22float2(*(__half2*)&nf.w);
        acc[4] += f0.x; acc[5] += f0.y;
        acc[6] += f1.x; acc[7] += f1.y;
        acc[8] += f2.x; acc[9] += f2.y;
        acc[10] += f3.x;
    }

#pragma unroll
    for (int off = 16; off; off >>= 1) {
#pragma unroll
        for (int k = 0; k < 11; k++)
            acc[k] += __shfl_xor_sync(0xffffffffu, acc[k], off);
    }

    float invd = 1.0f / fmaxf((float)deg, 1.0f);

    float y = sb1a[lane];
#pragma unroll
    for (int k = 0; k < 11; k++)
        y = fmaf(acc[k] * invd, sW1a[k * 32 + lane], y);
    y = fmaxf(y, 0.0f);

    float z = sb1b[lane];
#pragma unroll
    for (int k = 0; k < 32; k++) {
        float yk = __shfl_sync(0xffffffffu, y, k);
        z = fmaf(yk, sW1b[k * 32 + lane], z);
    }
    z = fmaxf(z, 0.0f);

    g_h1h[n * 32 + lane] = __float2half_rn(z);
}

// ---------------- layer 2: tail-free padded gather + smem float4 MLP, 6 blocks/SM ----------------
__global__ void __launch_bounds__(256, 6) node2_kernel(
        const float* __restrict__ W2a, const float* __restrict__ b2a,
        const float* __restrict__ W2b, const float* __restrict__ b2b,
        const int* __restrict__ graph_ids) {
    __shared__ float4 sWaT[256];    // [kq*32+lane] = {W2a[4kq+j][lane]}
    __shared__ float4 sWbT[256];
    __shared__ float  sb2a[32];
    __shared__ float  sb2b[32];
    __shared__ float  sX[8][32];
    int tid = threadIdx.x;
    for (int idx0 = tid; idx0 < 256; idx0 += blockDim.x) {
        int kq = idx0 >> 5, ln = idx0 & 31;
        sWaT[kq * 32 + ln] = make_float4(W2a[(4 * kq + 0) * 32 + ln],
                                         W2a[(4 * kq + 1) * 32 + ln],
                                         W2a[(4 * kq + 2) * 32 + ln],
                                         W2a[(4 * kq + 3) * 32 + ln]);
        sWbT[kq * 32 + ln] = make_float4(W2b[(4 * kq + 0) * 32 + ln],
                                         W2b[(4 * kq + 1) * 32 + ln],
                                         W2b[(4 * kq + 2) * 32 + ln],
                                         W2b[(4 * kq + 3) * 32 + ln]);
    }
    if (tid < 32) { sb2a[tid] = b2a[tid]; sb2b[tid] = b2b[tid]; }
    __syncthreads();

    int warp = tid >> 5;
    int lane = tid & 31;
    int n = blockIdx.x * 8 + warp;

    int start = g_off[n];
    int deg   = g_count[n];
    int pc    = (deg + 15) & ~15;   // padded count (dummies sum 0)

    int half = lane >> 4;     // 0: even edges, 1: odd edges
    int fl   = lane & 15;     // feature-pair index
    const __half2* h1p = (const __half2*)g_h1h;

    float2 a0 = make_float2(0.f, 0.f);
    float2 a1 = make_float2(0.f, 0.f);
    float2 a2 = make_float2(0.f, 0.f);
    float2 a3 = make_float2(0.f, 0.f);

    // software-pipelined, tail-free
    int idx = 0;
    if (lane < 16 && pc > 0) idx = (int)g_sorted[start + lane].x;
    for (int j = 0; j < pc; j += 16) {
        int r0 = __shfl_sync(0xffffffffu, idx,  0 + half);
        int r1 = __shfl_sync(0xffffffffu, idx,  2 + half);
        int r2 = __shfl_sync(0xffffffffu, idx,  4 + half);
        int r3 = __shfl_sync(0xffffffffu, idx,  6 + half);
        int r4 = __shfl_sync(0xffffffffu, idx,  8 + half);
        int r5 = __shfl_sync(0xffffffffu, idx, 10 + half);
        int r6 = __shfl_sync(0xffffffffu, idx, 12 + half);
        int r7 = __shfl_sync(0xffffffffu, idx, 14 + half);
        int nidx = 0;
        if (lane < 16 && j + 16 < pc)
            nidx = (int)g_sorted[start + j + 16 + lane].x;   // prefetch next round
        float2 v0 = __half22float2(__ldg(&h1p[r0 * 16 + fl]));
        float2 v1 = __half22float2(__ldg(&h1p[r1 * 16 + fl]));
        float2 v2 = __half22float2(__ldg(&h1p[r2 * 16 + fl]));
        float2 v3 = __half22float2(__ldg(&h1p[r3 * 16 + fl]));
        float2 v4 = __half22float2(__ldg(&h1p[r4 * 16 + fl]));
        float2 v5 = __half22float2(__ldg(&h1p[r5 * 16 + fl]));
        float2 v6 = __half22float2(__ldg(&h1p[r6 * 16 + fl]));
        float2 v7 = __half22float2(__ldg(&h1p[r7 * 16 + fl]));
        a0.x += v0.x + v4.x; a0.y += v0.y + v4.y;
        a1.x += v1.x + v5.x; a1.y += v1.y + v5.y;
        a2.x += v2.x + v6.x; a2.y += v2.y + v6.y;
        a3.x += v3.x + v7.x; a3.y += v3.y + v7.y;
        idx = nidx;
    }

    float2 accp;
    accp.x = (a0.x + a1.x) + (a2.x + a3.x);
    accp.y = (a0.y + a1.y) + (a2.y + a3.y);
    accp.x += __shfl_xor_sync(0xffffffffu, accp.x, 16);
    accp.y += __shfl_xor_sync(0xffffffffu, accp.y, 16);
    float xe = __shfl_sync(0xffffffffu, accp.x, lane >> 1);
    float xo = __shfl_sync(0xffffffffu, accp.y, lane >> 1);
    float x = ((lane & 1) ? xo : xe) / fmaxf((float)deg, 1.0f);

    // MLP layer a (smem staging + float4 weights)
    sX[warp][lane] = x;
    __syncwarp();
    float y = sb2a[lane];
#pragma unroll
    for (int kq = 0; kq < 8; kq++) {
        float4 xv = *(const float4*)&sX[warp][kq * 4];
        float4 w  = sWaT[kq * 32 + lane];
        y = fmaf(xv.x, w.x, y);
        y = fmaf(xv.y, w.y, y);
        y = fmaf(xv.z, w.z, y);
        y = fmaf(xv.w, w.w, y);
    }
    y = fmaxf(y, 0.0f);

    // MLP layer b
    __syncwarp();
    sX[warp][lane] = y;
    __syncwarp();
    float z = sb2b[lane];
#pragma unroll
    for (int kq = 0; kq < 8; kq++) {
        float4 xv = *(const float4*)&sX[warp][kq * 4];
        float4 w  = sWbT[kq * 32 + lane];
        z = fmaf(xv.x, w.x, z);
        z = fmaf(xv.y, w.y, z);
        z = fmaf(xv.z, w.z, z);
        z = fmaf(xv.w, w.w, z);
    }
    z = fmaxf(z, 0.0f);  // >= 0 -> int-compare atomicMax is order-safe

    int g = graph_ids[n];
    atomicMax((int*)&g_pooled[g * 32 + lane], __float_as_int(z));
}

// ---------------- classifier head ----------------
__global__ void head_kernel(const float* __restrict__ Wm1, const float* __restrict__ bm1,
                            const float* __restrict__ Wm2, const float* __restrict__ bm2,
                            float* __restrict__ out) {
    int g = threadIdx.x;
    if (g >= NG) return;
    float p[32];
#pragma unroll
    for (int k = 0; k < 32; k++) p[k] = g_pooled[g * 32 + k];
    float hid[16];
#pragma unroll
    for (int jj = 0; jj < 16; jj++) {
        float a = bm1[jj];
#pragma unroll
        for (int k = 0; k < 32; k++) a = fmaf(p[k], Wm1[k * 16 + jj], a);
        hid[jj] = fmaxf(a, 0.0f);
    }
    float l0 = bm2[0], l1 = bm2[1];
#pragma unroll
    for (int jj = 0; jj < 16; jj++) {
        l0 = fmaf(hid[jj], Wm2[jj * 2 + 0], l0);
        l1 = fmaf(hid[jj], Wm2[jj * 2 + 1], l1);
    }
    float m = fmaxf(l0, l1);
    float e0 = expf(l0 - m);
    float e1 = expf(l1 - m);
    float inv = 1.0f / (e0 + e1);
    out[g * 2 + 0] = e0 * inv;
    out[g * 2 + 1] = e1 * inv;
}

extern "C" void kernel_launch(void* const* d_in, const int* in_sizes, int n_in,
                              void* d_out, int out_size) {
    const float* node_feat = (const float*)d_in[0];
    const float* edge_feat = (const float*)d_in[1];
    const int*   src       = (const int*)d_in[2];
    const int*   dst       = (const int*)d_in[3];
    const int*   graph_ids = (const int*)d_in[4];
    const float* W1a = (const float*)d_in[5];
    const float* b1a = (const float*)d_in[6];
    const float* W1b = (const float*)d_in[7];
    const float* b1b = (const float*)d_in[8];
    const float* W2a = (const float*)d_in[9];
    const float* b2a = (const float*)d_in[10];
    const float* W2b = (const float*)d_in[11];
    const float* b2b = (const float*)d_in[12];
    const float* Wm1 = (const float*)d_in[13];
    const float* bm1 = (const float*)d_in[14];
    const float* Wm2 = (const float*)d_in[15];
    const float* bm2 = (const float*)d_in[16];
    float* out = (float*)d_out;

    setup_kernel<<<(NN * 8 + 255) / 256, 256>>>(node_feat);
    sort_kernel<<<NB_SCAN, 256>>>((const int4*)src, (const int4*)dst,
                                  (const float4*)edge_feat);
    node1_kernel<<<NN / 8, 256>>>(W1a, b1a, W1b, b1b);
    node2_kernel<<<NN / 8, 256>>>(W2a, b2a, W2b, b2b, graph_ids);
    head_kernel<<<1, 64>>>(Wm1, bm1, Wm2, bm2, out);
}

// round 15
// speedup vs baseline: 1.4174x; 1.0266x over previous
#include <cuda_runtime.h>
#include <cuda_fp16.h>
#include <stdint.h>
#include <math.h>

#define NN 200000
#define NE 6400000
#define NG 64
#define NB_SCAN 782   // ceil(NN/256); all blocks resident

// ---- device scratch (static, no runtime allocation) ----
__device__ int    g_count[NN];          // in-degree
__device__ int    g_off[NN];            // CSR offsets (exclusive scan)
__device__ int    g_rank[NE];           // per-edge rank within its dst bucket
__device__ int    g_bsum[1024];         // scan block totals
__device__ int    g_sync[4];            // global sync counters
__device__ uint4  g_sorted[NE + 16];    // {src, ef01, ef23, 0} sorted by dst (+slack)
__device__ __half g_nfh[NN * 8];        // node_feat as half, padded to 8/row (16B)
__device__ __half g_h1h[(NN + 1) * 32]; // layer-1 output (fp16); row NN = zeros (dummy)
__device__ float  g_pooled[NG * 32];

// ---------------- setup ----------------
__global__ void setup_kernel(const float* __restrict__ node_feat) {
    int i = blockIdx.x * blockDim.x + threadIdx.x;
    if (i < NN * 8) {
        int n = i >> 3, k = i & 7;
        g_nfh[i] = __float2half_rn((k < 7) ? node_feat[n * 7 + k] : 0.0f);
    }
    if (i < NN) g_count[i] = 0;
    if (i < NG * 32) g_pooled[i] = 0.0f;
    if (i < 32) g_h1h[NN * 32 + i] = __float2half_rn(0.0f);  // dummy zero row
    if (i < 16) g_sorted[NE + i] = make_uint4(0u, 0u, 0u, 0u);
    if (i < 4) g_sync[i] = 0;
}

__device__ __forceinline__ unsigned int pack_h2(float a, float b) {
    __half2 h = __floats2half2_rn(a, b);
    return *(unsigned int*)&h;
}

__device__ __forceinline__ void gsync(int idx) {
    __syncthreads();
    __threadfence();
    if (threadIdx.x == 0) {
        atomicAdd(&g_sync[idx], 1);
        while (atomicAdd(&g_sync[idx], 0) < NB_SCAN) { }
    }
    __syncthreads();
}

// ---------------- persistent sort: hist(+rank) -> scan -> atomic-free scatter ----------------
__global__ void sort_kernel(const int4* __restrict__ src4,
                            const int4* __restrict__ dst4,
                            const float4* __restrict__ ef4) {
    __shared__ int s[256];
    int t = threadIdx.x;
    int b = blockIdx.x;
    int i = b * 256 + t;
    const int nquads = NE / 4;
    int4* rank4 = (int4*)g_rank;

    // --- phase 0: histogram; atomic return value = rank within bucket ---
    for (int q = b * 256 + t; q < nquads; q += NB_SCAN * 256) {
        int4 d = dst4[q];
        int4 r;
        r.x = atomicAdd(&g_count[d.x], 1);
        r.y = atomicAdd(&g_count[d.y], 1);
        r.z = atomicAdd(&g_count[d.z], 1);
        r.w = atomicAdd(&g_count[d.w], 1);
        rank4[q] = r;
    }
    gsync(0);

    // --- phase 1: block-local inclusive scan of degrees ---
    int v = (i < NN) ? g_count[i] : 0;
    s[t] = v;
    __syncthreads();
    for (int off = 1; off < 256; off <<= 1) {
        int add = (t >= off) ? s[t - off] : 0;
        __syncthreads();
        s[t] += add;
        __syncthreads();
    }
    int local_excl = s[t] - v;
    if (t == 255) {
        g_bsum[b] = s[255];
        __threadfence();
        atomicAdd(&g_sync[1], 1);
    }
    if (t == 0) { while (atomicAdd(&g_sync[1], 0) < NB_SCAN) { } }
    __syncthreads();

    // --- phase 2: block prefix from published totals ---
    int pre = 0;
    for (int k = t; k < b; k += 256) pre += g_bsum[k];
    s[t] = pre;
    __syncthreads();
    for (int o = 128; o; o >>= 1) {
        if (t < o) s[t] += s[t + o];
        __syncthreads();
    }
    if (i < NN) g_off[i] = s[0] + local_excl;

    gsync(2);

    // --- phase 3: scatter, NO atomics: pos = off[dst] + rank ---
    for (int q = b * 256 + t; q < nquads; q += NB_SCAN * 256) {
        int4 sv = src4[q];
        int4 dv = dst4[q];
        int4 rv = rank4[q];
        float4 e0 = ef4[q * 4 + 0];
        float4 e1 = ef4[q * 4 + 1];
        float4 e2 = ef4[q * 4 + 2];
        float4 e3 = ef4[q * 4 + 3];
        uint4 w;
        w.w = 0u;

        w.x = (unsigned int)sv.x; w.y = pack_h2(e0.x, e0.y); w.z = pack_h2(e0.z, e0.w);
        g_sorted[g_off[dv.x] + rv.x] = w;
        w.x = (unsigned int)sv.y; w.y = pack_h2(e1.x, e1.y); w.z = pack_h2(e1.z, e1.w);
        g_sorted[g_off[dv.y] + rv.y] = w;
        w.x = (unsigned int)sv.z; w.y = pack_h2(e2.x, e2.y); w.z = pack_h2(e2.z, e2.w);
        g_sorted[g_off[dv.z] + rv.z] = w;
        w.x = (unsigned int)sv.w; w.y = pack_h2(e3.x, e3.y); w.z = pack_h2(e3.z, e3.w);
        g_sorted[g_off[dv.w] + rv.w] = w;
    }
}

// ---------------- layer 1 (R8 proven form): edge stream + one fp16 nf gather ----------------
__global__ void node1_kernel(const float* __restrict__ W1a, const float* __restrict__ b1a,
                             const float* __restrict__ W1b, const float* __restrict__ b1b) {
    __shared__ float sW1a[11 * 32];
    __shared__ float sW1b[32 * 32];
    __shared__ float sb1a[32];
    __shared__ float sb1b[32];
    int tid = threadIdx.x;
    for (int k = tid; k < 11 * 32; k += blockDim.x) sW1a[k] = W1a[k];
    for (int k = tid; k < 32 * 32; k += blockDim.x) sW1b[k] = W1b[k];
    if (tid < 32) { sb1a[tid] = b1a[tid]; sb1b[tid] = b1b[tid]; }
    __syncthreads();

    int warp = tid >> 5;
    int lane = tid & 31;
    int n = blockIdx.x * 8 + warp;

    int start = g_off[n];
    int deg   = g_count[n];

    float acc[11];
#pragma unroll
    for (int k = 0; k < 11; k++) acc[k] = 0.0f;

    const uint4* nfq = (const uint4*)g_nfh;
    for (int j = lane; j < deg; j += 32) {
        uint4 p = __ldg(&g_sorted[start + j]);   // coalesced 16B stream
        float2 e01 = __half22float2(*(__half2*)&p.y);
        float2 e23 = __half22float2(*(__half2*)&p.z);
        acc[0] += e01.x; acc[1] += e01.y; acc[2] += e23.x; acc[3] += e23.y;
        uint4 nf = __ldg(&nfq[p.x]);             // ONE 16B gather (L2-resident)
        float2 f0 = __half22float2(*(__half2*)&nf.x);
        float2 f1 = __half22float2(*(__half2*)&nf.y);
        float2 f2 = __half22float2(*(__half2*)&nf.z);
        float2 f3 = __half22float2(*(__half2*)&nf.w);
        acc[4] += f0.x; acc[5] += f0.y;
        acc[6] += f1.x; acc[7] += f1.y;
        acc[8] += f2.x; acc[9] += f2.y;
        acc[10] += f3.x;
    }

#pragma unroll
    for (int off = 16; off; off >>= 1) {
#pragma unroll
        for (int k = 0; k < 11; k++)
            acc[k] += __shfl_xor_sync(0xffffffffu, acc[k], off);
    }

    float invd = 1.0f / fmaxf((float)deg, 1.0f);

    float y = sb1a[lane];
#pragma unroll
    for (int k = 0; k < 11; k++)
        y = fmaf(acc[k] * invd, sW1a[k * 32 + lane], y);
    y = fmaxf(y, 0.0f);

    float z = sb1b[lane];
#pragma unroll
    for (int k = 0; k < 32; k++) {
        float yk = __shfl_sync(0xffffffffu, y, k);
        z = fmaf(yk, sW1b[k * 32 + lane], z);
    }
    z = fmaxf(z, 0.0f);

    g_h1h[n * 32 + lane] = __float2half_rn(z);
}

// ---------------- layer 2: uint4 row gather (8 edges/LDG.128) + smem float4 MLP ----------------
__global__ void __launch_bounds__(256, 6) node2_kernel(
        const float* __restrict__ W2a, const float* __restrict__ b2a,
        const float* __restrict__ W2b, const float* __restrict__ b2b,
        const int* __restrict__ graph_ids) {
    __shared__ float4 sWaT[256];    // [kq*32+lane] = {W2a[4kq+j][lane]}
    __shared__ float4 sWbT[256];
    __shared__ float  sb2a[32];
    __shared__ float  sb2b[32];
    __shared__ float  sX[8][32];
    int tid = threadIdx.x;
    for (int idx0 = tid; idx0 < 256; idx0 += blockDim.x) {
        int kq = idx0 >> 5, ln = idx0 & 31;
        sWaT[kq * 32 + ln] = make_float4(W2a[(4 * kq + 0) * 32 + ln],
                                         W2a[(4 * kq + 1) * 32 + ln],
                                         W2a[(4 * kq + 2) * 32 + ln],
                                         W2a[(4 * kq + 3) * 32 + ln]);
        sWbT[kq * 32 + ln] = make_float4(W2b[(4 * kq + 0) * 32 + ln],
                                         W2b[(4 * kq + 1) * 32 + ln],
                                         W2b[(4 * kq + 2) * 32 + ln],
                                         W2b[(4 * kq + 3) * 32 + ln]);
    }
    if (tid < 32) { sb2a[tid] = b2a[tid]; sb2b[tid] = b2b[tid]; }
    __syncthreads();

    int warp = tid >> 5;
    int lane = tid & 31;
    int n = blockIdx.x * 8 + warp;

    int start = g_off[n];
    int deg   = g_count[n];

    int q = lane & 3;    // 16B quarter of the 64B h1 row (features q*8 .. q*8+7)
    int e = lane >> 2;   // edge-within-group 0..7
    const uint4* h1q = (const uint4*)g_h1h;

    float2 a0 = make_float2(0.f, 0.f);
    float2 a1 = make_float2(0.f, 0.f);
    float2 a2 = make_float2(0.f, 0.f);
    float2 a3 = make_float2(0.f, 0.f);

    for (int j = 0; j < deg; j += 16) {
        int idx = 0;
        if (lane < 16) idx = (int)g_sorted[start + j + lane].x;  // slack-safe
#pragma unroll
        for (int rr = 0; rr < 2; rr++) {
            int eg = rr * 8 + e;
            int srcE = __shfl_sync(0xffffffffu, idx, eg);
            srcE = (j + eg < deg) ? srcE : NN;   // masked -> dummy zero row
            uint4 v = __ldg(&h1q[srcE * 4 + q]); // ONE LDG.128 covers 8 edges
            float2 f0 = __half22float2(*(__half2*)&v.x);
            float2 f1 = __half22float2(*(__half2*)&v.y);
            float2 f2 = __half22float2(*(__half2*)&v.z);
            float2 f3 = __half22float2(*(__half2*)&v.w);
            a0.x += f0.x; a0.y += f0.y;
            a1.x += f1.x; a1.y += f1.y;
            a2.x += f2.x; a2.y += f2.y;
            a3.x += f3.x; a3.y += f3.y;
        }
    }

    // reduce across the 8 edge-lanes sharing this q (partners at xor 4, 8, 16)
#pragma unroll
    for (int off = 4; off <= 16; off <<= 1) {
        a0.x += __shfl_xor_sync(0xffffffffu, a0.x, off);
        a0.y += __shfl_xor_sync(0xffffffffu, a0.y, off);
        a1.x += __shfl_xor_sync(0xffffffffu, a1.x, off);
        a1.y += __shfl_xor_sync(0xffffffffu, a1.y, off);
        a2.x += __shfl_xor_sync(0xffffffffu, a2.x, off);
        a2.y += __shfl_xor_sync(0xffffffffu, a2.y, off);
        a3.x += __shfl_xor_sync(0xffffffffu, a3.x, off);
        a3.y += __shfl_xor_sync(0xffffffffu, a3.y, off);
    }

    // lanes 0-3 (e==0) publish the scaled mean: sX[warp][q*8+k]
    float invd = 1.0f / fmaxf((float)deg, 1.0f);
    if (e == 0) {
        sX[warp][q * 8 + 0] = a0.x * invd;
        sX[warp][q * 8 + 1] = a0.y * invd;
        sX[warp][q * 8 + 2] = a1.x * invd;
        sX[warp][q * 8 + 3] = a1.y * invd;
        sX[warp][q * 8 + 4] = a2.x * invd;
        sX[warp][q * 8 + 5] = a2.y * invd;
        sX[warp][q * 8 + 6] = a3.x * invd;
        sX[warp][q * 8 + 7] = a3.y * invd;
    }
    __syncwarp();

    // MLP layer a (x already staged in sX)
    float y = sb2a[lane];
#pragma unroll
    for (int kq = 0; kq < 8; kq++) {
        float4 xv = *(const float4*)&sX[warp][kq * 4];
        float4 w  = sWaT[kq * 32 + lane];
        y = fmaf(xv.x, w.x, y);
        y = fmaf(xv.y, w.y, y);
        y = fmaf(xv.z, w.z, y);
        y = fmaf(xv.w, w.w, y);
    }
    y = fmaxf(y, 0.0f);

    // MLP layer b
    __syncwarp();
    sX[warp][lane] = y;
    __syncwarp();
    float z = sb2b[lane];
#pragma unroll
    for (int kq = 0; kq < 8; kq++) {
        float4 xv = *(const float4*)&sX[warp][kq * 4];
        float4 w  = sWbT[kq * 32 + lane];
        z = fmaf(xv.x, w.x, z);
        z = fmaf(xv.y, w.y, z);
        z = fmaf(xv.z, w.z, z);
        z = fmaf(xv.w, w.w, z);
    }
    z = fmaxf(z, 0.0f);  // >= 0 -> int-compare atomicMax is order-safe

    int g = graph_ids[n];
    atomicMax((int*)&g_pooled[g * 32 + lane], __float_as_int(z));
}

// ---------------- classifier head ----------------
__global__ void head_kernel(const float* __restrict__ Wm1, const float* __restrict__ bm1,
                            const float* __restrict__ Wm2, const float* __restrict__ bm2,
                            float* __restrict__ out) {
    int g = threadIdx.x;
    if (g >= NG) return;
    float p[32];
#pragma unroll
    for (int k = 0; k < 32; k++) p[k] = g_pooled[g * 32 + k];
    float hid[16];
#pragma unroll
    for (int jj = 0; jj < 16; jj++) {
        float a = bm1[jj];
#pragma unroll
        for (int k = 0; k < 32; k++) a = fmaf(p[k], Wm1[k * 16 + jj], a);
        hid[jj] = fmaxf(a, 0.0f);
    }
    float l0 = bm2[0], l1 = bm2[1];
#pragma unroll
    for (int jj = 0; jj < 16; jj++) {
        l0 = fmaf(hid[jj], Wm2[jj * 2 + 0], l0);
        l1 = fmaf(hid[jj], Wm2[jj * 2 + 1], l1);
    }
    float m = fmaxf(l0, l1);
    float e0 = expf(l0 - m);
    float e1 = expf(l1 - m);
    float inv = 1.0f / (e0 + e1);
    out[g * 2 + 0] = e0 * inv;
    out[g * 2 + 1] = e1 * inv;
}

extern "C" void kernel_launch(void* const* d_in, const int* in_sizes, int n_in,
                              void* d_out, int out_size) {
    const float* node_feat = (const float*)d_in[0];
    const float* edge_feat = (const float*)d_in[1];
    const int*   src       = (const int*)d_in[2];
    const int*   dst       = (const int*)d_in[3];
    const int*   graph_ids = (const int*)d_in[4];
    const float* W1a = (const float*)d_in[5];
    const float* b1a = (const float*)d_in[6];
    const float* W1b = (const float*)d_in[7];
    const float* b1b = (const float*)d_in[8];
    const float* W2a = (const float*)d_in[9];
    const float* b2a = (const float*)d_in[10];
    const float* W2b = (const float*)d_in[11];
    const float* b2b = (const float*)d_in[12];
    const float* Wm1 = (const float*)d_in[13];
    const float* bm1 = (const float*)d_in[14];
    const float* Wm2 = (const float*)d_in[15];
    const float* bm2 = (const float*)d_in[16];
    float* out = (float*)d_out;

    setup_kernel<<<(NN * 8 + 255) / 256, 256>>>(node_feat);
    sort_kernel<<<NB_SCAN, 256>>>((const int4*)src, (const int4*)dst,
                                  (const float4*)edge_feat);
    node1_kernel<<<NN / 8, 256>>>(W1a, b1a, W1b, b1b);
    node2_kernel<<<NN / 8, 256>>>(W2a, b2a, W2b, b2b, graph_ids);
    head_kernel<<<1, 64>>>(Wm1, bm1, Wm2, bm2, out);
}

// round 16
// speedup vs baseline: 1.4381x; 1.0146x over previous
#include <cuda_runtime.h>
#include <cuda_fp16.h>
#include <stdint.h>
#include <math.h>

#define NN 200000
#define NE 6400000
#define NG 64
#define NB_SCAN 782   // ceil(NN/256); all blocks resident

// ---- device scratch (static, no runtime allocation) ----
__device__ int    g_count[NN];          // in-degree
__device__ int    g_off[NN];            // CSR offsets (exclusive scan)
__device__ int    g_rank[NE];           // per-edge rank within its dst bucket
__device__ int    g_bsum[1024];         // scan block totals
__device__ int    g_sync[4];            // global sync counters
__device__ uint4  g_sorted[NE + 32];    // {src, ef01, ef23, 0} sorted by dst (+slack)
__device__ __half g_nfh[NN * 8];        // node_feat as half, padded to 8/row (16B)
__device__ __half g_h1h[(NN + 1) * 32]; // layer-1 output (fp16); row NN = zeros (dummy)
__device__ float  g_pooled[NG * 32];

// ---------------- setup ----------------
__global__ void setup_kernel(const float* __restrict__ node_feat) {
    int i = blockIdx.x * blockDim.x + threadIdx.x;
    if (i < NN * 8) {
        int n = i >> 3, k = i & 7;
        g_nfh[i] = __float2half_rn((k < 7) ? node_feat[n * 7 + k] : 0.0f);
    }
    if (i < NN) g_count[i] = 0;
    if (i < NG * 32) g_pooled[i] = 0.0f;
    if (i < 32) g_h1h[NN * 32 + i] = __float2half_rn(0.0f);  // dummy zero row
    if (i < 32) g_sorted[NE + i] = make_uint4(0u, 0u, 0u, 0u);
    if (i < 4) g_sync[i] = 0;
}

__device__ __forceinline__ unsigned int pack_h2(float a, float b) {
    __half2 h = __floats2half2_rn(a, b);
    return *(unsigned int*)&h;
}

__device__ __forceinline__ void gsync(int idx) {
    __syncthreads();
    __threadfence();
    if (threadIdx.x == 0) {
        atomicAdd(&g_sync[idx], 1);
        while (atomicAdd(&g_sync[idx], 0) < NB_SCAN) { }
    }
    __syncthreads();
}

// ---------------- persistent sort: hist(+rank) -> scan -> atomic-free scatter ----------------
__global__ void sort_kernel(const int4* __restrict__ src4,
                            const int4* __restrict__ dst4,
                            const float4* __restrict__ ef4) {
    __shared__ int s[256];
    int t = threadIdx.x;
    int b = blockIdx.x;
    int i = b * 256 + t;
    const int nquads = NE / 4;
    int4* rank4 = (int4*)g_rank;

    // --- phase 0: histogram; atomic return value = rank within bucket ---
    for (int q = b * 256 + t; q < nquads; q += NB_SCAN * 256) {
        int4 d = dst4[q];
        int4 r;
        r.x = atomicAdd(&g_count[d.x], 1);
        r.y = atomicAdd(&g_count[d.y], 1);
        r.z = atomicAdd(&g_count[d.z], 1);
        r.w = atomicAdd(&g_count[d.w], 1);
        rank4[q] = r;
    }
    gsync(0);

    // --- phase 1: block-local inclusive scan of degrees ---
    int v = (i < NN) ? g_count[i] : 0;
    s[t] = v;
    __syncthreads();
    for (int off = 1; off < 256; off <<= 1) {
        int add = (t >= off) ? s[t - off] : 0;
        __syncthreads();
        s[t] += add;
        __syncthreads();
    }
    int local_excl = s[t] - v;
    if (t == 255) {
        g_bsum[b] = s[255];
        __threadfence();
        atomicAdd(&g_sync[1], 1);
    }
    if (t == 0) { while (atomicAdd(&g_sync[1], 0) < NB_SCAN) { } }
    __syncthreads();

    // --- phase 2: block prefix from published totals ---
    int pre = 0;
    for (int k = t; k < b; k += 256) pre += g_bsum[k];
    s[t] = pre;
    __syncthreads();
    for (int o = 128; o; o >>= 1) {
        if (t < o) s[t] += s[t + o];
        __syncthreads();
    }
    if (i < NN) g_off[i] = s[0] + local_excl;

    gsync(2);

    // --- phase 3: scatter, NO atomics: pos = off[dst] + rank ---
    for (int q = b * 256 + t; q < nquads; q += NB_SCAN * 256) {
        int4 sv = src4[q];
        int4 dv = dst4[q];
        int4 rv = rank4[q];
        float4 e0 = ef4[q * 4 + 0];
        float4 e1 = ef4[q * 4 + 1];
        float4 e2 = ef4[q * 4 + 2];
        float4 e3 = ef4[q * 4 + 3];
        uint4 w;
        w.w = 0u;

        w.x = (unsigned int)sv.x; w.y = pack_h2(e0.x, e0.y); w.z = pack_h2(e0.z, e0.w);
        g_sorted[g_off[dv.x] + rv.x] = w;
        w.x = (unsigned int)sv.y; w.y = pack_h2(e1.x, e1.y); w.z = pack_h2(e1.z, e1.w);
        g_sorted[g_off[dv.y] + rv.y] = w;
        w.x = (unsigned int)sv.z; w.y = pack_h2(e2.x, e2.y); w.z = pack_h2(e2.z, e2.w);
        g_sorted[g_off[dv.z] + rv.z] = w;
        w.x = (unsigned int)sv.w; w.y = pack_h2(e3.x, e3.y); w.z = pack_h2(e3.z, e3.w);
        g_sorted[g_off[dv.w] + rv.w] = w;
    }
}

// ---------------- layer 1 (R8 proven form): edge stream + one fp16 nf gather ----------------
__global__ void node1_kernel(const float* __restrict__ W1a, const float* __restrict__ b1a,
                             const float* __restrict__ W1b, const float* __restrict__ b1b) {
    __shared__ float sW1a[11 * 32];
    __shared__ float sW1b[32 * 32];
    __shared__ float sb1a[32];
    __shared__ float sb1b[32];
    int tid = threadIdx.x;
    for (int k = tid; k < 11 * 32; k += blockDim.x) sW1a[k] = W1a[k];
    for (int k = tid; k < 32 * 32; k += blockDim.x) sW1b[k] = W1b[k];
    if (tid < 32) { sb1a[tid] = b1a[tid]; sb1b[tid] = b1b[tid]; }
    __syncthreads();

    int warp = tid >> 5;
    int lane = tid & 31;
    int n = blockIdx.x * 8 + warp;

    int start = g_off[n];
    int deg   = g_count[n];

    float acc[11];
#pragma unroll
    for (int k = 0; k < 11; k++) acc[k] = 0.0f;

    const uint4* nfq = (const uint4*)g_nfh;
    for (int j = lane; j < deg; j += 32) {
        uint4 p = __ldg(&g_sorted[start + j]);   // coalesced 16B stream
        float2 e01 = __half22float2(*(__half2*)&p.y);
        float2 e23 = __half22float2(*(__half2*)&p.z);
        acc[0] += e01.x; acc[1] += e01.y; acc[2] += e23.x; acc[3] += e23.y;
        uint4 nf = __ldg(&nfq[p.x]);             // ONE 16B gather (L2-resident)
        float2 f0 = __half22float2(*(__half2*)&nf.x);
        float2 f1 = __half22float2(*(__half2*)&nf.y);
        float2 f2 = __half22float2(*(__half2*)&nf.z);
        float2 f3 = __half22float2(*(__half2*)&nf.w);
        acc[4] += f0.x; acc[5] += f0.y;
        acc[6] += f1.x; acc[7] += f1.y;
        acc[8] += f2.x; acc[9] += f2.y;
        acc[10] += f3.x;
    }

#pragma unroll
    for (int off = 16; off; off >>= 1) {
#pragma unroll
        for (int k = 0; k < 11; k++)
            acc[k] += __shfl_xor_sync(0xffffffffu, acc[k], off);
    }

    float invd = 1.0f / fmaxf((float)deg, 1.0f);

    float y = sb1a[lane];
#pragma unroll
    for (int k = 0; k < 11; k++)
        y = fmaf(acc[k] * invd, sW1a[k * 32 + lane], y);
    y = fmaxf(y, 0.0f);

    float z = sb1b[lane];
#pragma unroll
    for (int k = 0; k < 32; k++) {
        float yk = __shfl_sync(0xffffffffu, y, k);
        z = fmaf(yk, sW1b[k * 32 + lane], z);
    }
    z = fmaxf(z, 0.0f);

    g_h1h[n * 32 + lane] = __float2half_rn(z);
}

// ---------------- layer 2: pipelined uint4 row gather + smem float4 MLP ----------------
__global__ void __launch_bounds__(256, 6) node2_kernel(
        const float* __restrict__ W2a, const float* __restrict__ b2a,
        const float* __restrict__ W2b, const float* __restrict__ b2b,
        const int* __restrict__ graph_ids) {
    __shared__ float4 sWaT[256];    // [kq*32+lane] = {W2a[4kq+j][lane]}
    __shared__ float4 sWbT[256];
    __shared__ float  sb2a[32];
    __shared__ float  sb2b[32];
    __shared__ float  sX[8][32];
    int tid = threadIdx.x;
    for (int idx0 = tid; idx0 < 256; idx0 += blockDim.x) {
        int kq = idx0 >> 5, ln = idx0 & 31;
        sWaT[kq * 32 + ln] = make_float4(W2a[(4 * kq + 0) * 32 + ln],
                                         W2a[(4 * kq + 1) * 32 + ln],
                                         W2a[(4 * kq + 2) * 32 + ln],
                                         W2a[(4 * kq + 3) * 32 + ln]);
        sWbT[kq * 32 + ln] = make_float4(W2b[(4 * kq + 0) * 32 + ln],
                                         W2b[(4 * kq + 1) * 32 + ln],
                                         W2b[(4 * kq + 2) * 32 + ln],
                                         W2b[(4 * kq + 3) * 32 + ln]);
    }
    if (tid < 32) { sb2a[tid] = b2a[tid]; sb2b[tid] = b2b[tid]; }
    __syncthreads();

    int warp = tid >> 5;
    int lane = tid & 31;
    int n = blockIdx.x * 8 + warp;

    int start = g_off[n];
    int deg   = g_count[n];

    int q = lane & 3;    // 16B quarter of the 64B h1 row (features q*8 .. q*8+7)
    int e = lane >> 2;   // edge-within-group 0..7
    const uint4* h1q = (const uint4*)g_h1h;

    float2 a0 = make_float2(0.f, 0.f);
    float2 a1 = make_float2(0.f, 0.f);
    float2 a2 = make_float2(0.f, 0.f);
    float2 a3 = make_float2(0.f, 0.f);

    // software-pipelined: prefetch next round's indices during this round's gathers
    int idx = 0;
    if (lane < 16 && deg > 0) idx = (int)g_sorted[start + lane].x;   // slack-safe
    for (int j = 0; j < deg; j += 16) {
        int nidx = 0;
        if (lane < 16 && j + 16 < deg)
            nidx = (int)g_sorted[start + j + 16 + lane].x;           // prefetch
#pragma unroll
        for (int rr = 0; rr < 2; rr++) {
            int eg = rr * 8 + e;
            int srcE = __shfl_sync(0xffffffffu, idx, eg);
            srcE = (j + eg < deg) ? srcE : NN;   // masked -> dummy zero row
            uint4 v = __ldg(&h1q[srcE * 4 + q]); // ONE LDG.128 covers 8 edges
            float2 f0 = __half22float2(*(__half2*)&v.x);
            float2 f1 = __half22float2(*(__half2*)&v.y);
            float2 f2 = __half22float2(*(__half2*)&v.z);
            float2 f3 = __half22float2(*(__half2*)&v.w);
            a0.x += f0.x; a0.y += f0.y;
            a1.x += f1.x; a1.y += f1.y;
            a2.x += f2.x; a2.y += f2.y;
            a3.x += f3.x; a3.y += f3.y;
        }
        idx = nidx;
    }

    // reduce across the 8 edge-lanes sharing this q (partners at xor 4, 8, 16)
#pragma unroll
    for (int off = 4; off <= 16; off <<= 1) {
        a0.x += __shfl_xor_sync(0xffffffffu, a0.x, off);
        a0.y += __shfl_xor_sync(0xffffffffu, a0.y, off);
        a1.x += __shfl_xor_sync(0xffffffffu, a1.x, off);
        a1.y += __shfl_xor_sync(0xffffffffu, a1.y, off);
        a2.x += __shfl_xor_sync(0xffffffffu, a2.x, off);
        a2.y += __shfl_xor_sync(0xffffffffu, a2.y, off);
        a3.x += __shfl_xor_sync(0xffffffffu, a3.x, off);
        a3.y += __shfl_xor_sync(0xffffffffu, a3.y, off);
    }

    // lanes 0-3 (e==0) publish the scaled mean: sX[warp][q*8+k]
    float invd = 1.0f / fmaxf((float)deg, 1.0f);
    if (e == 0) {
        sX[warp][q * 8 + 0] = a0.x * invd;
        sX[warp][q * 8 + 1] = a0.y * invd;
        sX[warp][q * 8 + 2] = a1.x * invd;
        sX[warp][q * 8 + 3] = a1.y * invd;
        sX[warp][q * 8 + 4] = a2.x * invd;
        sX[warp][q * 8 + 5] = a2.y * invd;
        sX[warp][q * 8 + 6] = a3.x * invd;
        sX[warp][q * 8 + 7] = a3.y * invd;
    }
    __syncwarp();

    // MLP layer a (x staged in sX)
    float y = sb2a[lane];
#pragma unroll
    for (int kq = 0; kq < 8; kq++) {
        float4 xv = *(const float4*)&sX[warp][kq * 4];
        float4 w  = sWaT[kq * 32 + lane];
        y = fmaf(xv.x, w.x, y);
        y = fmaf(xv.y, w.y, y);
        y = fmaf(xv.z, w.z, y);
        y = fmaf(xv.w, w.w, y);
    }
    y = fmaxf(y, 0.0f);

    // MLP layer b
    __syncwarp();
    sX[warp][lane] = y;
    __syncwarp();
    float z = sb2b[lane];
#pragma unroll
    for (int kq = 0; kq < 8; kq++) {
        float4 xv = *(const float4*)&sX[warp][kq * 4];
        float4 w  = sWbT[kq * 32 + lane];
        z = fmaf(xv.x, w.x, z);
        z = fmaf(xv.y, w.y, z);
        z = fmaf(xv.z, w.z, z);
        z = fmaf(xv.w, w.w, z);
    }
    z = fmaxf(z, 0.0f);  // >= 0 -> int-compare atomicMax is order-safe

    int g = graph_ids[n];
    atomicMax((int*)&g_pooled[g * 32 + lane], __float_as_int(z));
}

// ---------------- classifier head ----------------
__global__ void head_kernel(const float* __restrict__ Wm1, const float* __restrict__ bm1,
                            const float* __restrict__ Wm2, const float* __restrict__ bm2,
                            float* __restrict__ out) {
    int g = threadIdx.x;
    if (g >= NG) return;
    float p[32];
#pragma unroll
    for (int k = 0; k < 32; k++) p[k] = g_pooled[g * 32 + k];
    float hid[16];
#pragma unroll
    for (int jj = 0; jj < 16; jj++) {
        float a = bm1[jj];
#pragma unroll
        for (int k = 0; k < 32; k++) a = fmaf(p[k], Wm1[k * 16 + jj], a);
        hid[jj] = fmaxf(a, 0.0f);
    }
    float l0 = bm2[0], l1 = bm2[1];
#pragma unroll
    for (int jj = 0; jj < 16; jj++) {
        l0 = fmaf(hid[jj], Wm2[jj * 2 + 0], l0);
        l1 = fmaf(hid[jj], Wm2[jj * 2 + 1], l1);
    }
    float m = fmaxf(l0, l1);
    float e0 = expf(l0 - m);
    float e1 = expf(l1 - m);
    float inv = 1.0f / (e0 + e1);
    out[g * 2 + 0] = e0 * inv;
    out[g * 2 + 1] = e1 * inv;
}

extern "C" void kernel_launch(void* const* d_in, const int* in_sizes, int n_in,
                              void* d_out, int out_size) {
    const float* node_feat = (const float*)d_in[0];
    const float* edge_feat = (const float*)d_in[1];
    const int*   src       = (const int*)d_in[2];
    const int*   dst       = (const int*)d_in[3];
    const int*   graph_ids = (const int*)d_in[4];
    const float* W1a = (const float*)d_in[5];
    const float* b1a = (const float*)d_in[6];
    const float* W1b = (const float*)d_in[7];
    const float* b1b = (const float*)d_in[8];
    const float* W2a = (const float*)d_in[9];
    const float* b2a = (const float*)d_in[10];
    const float* W2b = (const float*)d_in[11];
    const float* b2b = (const float*)d_in[12];
    const float* Wm1 = (const float*)d_in[13];
    const float* bm1 = (const float*)d_in[14];
    const float* Wm2 = (const float*)d_in[15];
    const float* bm2 = (const float*)d_in[16];
    float* out = (float*)d_out;

    setup_kernel<<<(NN * 8 + 255) / 256, 256>>>(node_feat);
    sort_kernel<<<NB_SCAN, 256>>>((const int4*)src, (const int4*)dst,
                                  (const float4*)edge_feat);
    node1_kernel<<<NN / 8, 256>>>(W1a, b1a, W1b, b1b);
    node2_kernel<<<NN / 8, 256>>>(W2a, b2a, W2b, b2b, graph_ids);
    head_kernel<<<1, 64>>>(Wm1, bm1, Wm2, bm2, out);
}

// round 17
// speedup vs baseline: 1.4609x; 1.0159x over previous
#include <cuda_runtime.h>
#include <cuda_fp16.h>
#include <stdint.h>
#include <math.h>

#define NN 200000
#define NE 6400000
#define NG 64
#define NB_SCAN 782   // ceil(NN/256); all blocks resident

// ---- device scratch (static, no runtime allocation) ----
__device__ int    g_count[NN];          // in-degree
__device__ int    g_off[NN];            // CSR offsets (exclusive scan)
__device__ int    g_rank[NE];           // per-edge rank within its dst bucket
__device__ int    g_bsum[1024];         // scan block totals
__device__ int    g_sync[4];            // global sync counters
__device__ uint4  g_sorted[NE + 64];    // {src, ef01, ef23, 0} sorted by dst (+slack)
__device__ __half g_nfh[NN * 8];        // node_feat as half, padded to 8/row (16B)
__device__ __half g_h1h[(NN + 1) * 32]; // layer-1 output (fp16); row NN = zeros (dummy)
__device__ float  g_pooled[NG * 32];

// ---------------- setup ----------------
__global__ void setup_kernel(const float* __restrict__ node_feat) {
    int i = blockIdx.x * blockDim.x + threadIdx.x;
    if (i < NN * 8) {
        int n = i >> 3, k = i & 7;
        g_nfh[i] = __float2half_rn((k < 7) ? node_feat[n * 7 + k] : 0.0f);
    }
    if (i < NN) g_count[i] = 0;
    if (i < NG * 32) g_pooled[i] = 0.0f;
    if (i < 32) g_h1h[NN * 32 + i] = __float2half_rn(0.0f);  // dummy zero row
    if (i < 64) g_sorted[NE + i] = make_uint4(0u, 0u, 0u, 0u);
    if (i < 4) g_sync[i] = 0;
}

__device__ __forceinline__ unsigned int pack_h2(float a, float b) {
    __half2 h = __floats2half2_rn(a, b);
    return *(unsigned int*)&h;
}

__device__ __forceinline__ void gsync(int idx) {
    __syncthreads();
    __threadfence();
    if (threadIdx.x == 0) {
        atomicAdd(&g_sync[idx], 1);
        while (atomicAdd(&g_sync[idx], 0) < NB_SCAN) { }
    }
    __syncthreads();
}

// ---------------- persistent sort: hist(+rank) -> scan -> atomic-free scatter ----------------
__global__ void sort_kernel(const int4* __restrict__ src4,
                            const int4* __restrict__ dst4,
                            const float4* __restrict__ ef4) {
    __shared__ int s[256];
    int t = threadIdx.x;
    int b = blockIdx.x;
    int i = b * 256 + t;
    const int nquads = NE / 4;
    int4* rank4 = (int4*)g_rank;

    // --- phase 0: histogram; atomic return value = rank within bucket ---
    for (int q = b * 256 + t; q < nquads; q += NB_SCAN * 256) {
        int4 d = dst4[q];
        int4 r;
        r.x = atomicAdd(&g_count[d.x], 1);
        r.y = atomicAdd(&g_count[d.y], 1);
        r.z = atomicAdd(&g_count[d.z], 1);
        r.w = atomicAdd(&g_count[d.w], 1);
        rank4[q] = r;
    }
    gsync(0);

    // --- phase 1: block-local inclusive scan of degrees ---
    int v = (i < NN) ? g_count[i] : 0;
    s[t] = v;
    __syncthreads();
    for (int off = 1; off < 256; off <<= 1) {
        int add = (t >= off) ? s[t - off] : 0;
        __syncthreads();
        s[t] += add;
        __syncthreads();
    }
    int local_excl = s[t] - v;
    if (t == 255) {
        g_bsum[b] = s[255];
        __threadfence();
        atomicAdd(&g_sync[1], 1);
    }
    if (t == 0) { while (atomicAdd(&g_sync[1], 0) < NB_SCAN) { } }
    __syncthreads();

    // --- phase 2: block prefix from published totals ---
    int pre = 0;
    for (int k = t; k < b; k += 256) pre += g_bsum[k];
    s[t] = pre;
    __syncthreads();
    for (int o = 128; o; o >>= 1) {
        if (t < o) s[t] += s[t + o];
        __syncthreads();
    }
    if (i < NN) g_off[i] = s[0] + local_excl;

    gsync(2);

    // --- phase 3: scatter, NO atomics: pos = off[dst] + rank ---
    for (int q = b * 256 + t; q < nquads; q += NB_SCAN * 256) {
        int4 sv = src4[q];
        int4 dv = dst4[q];
        int4 rv = rank4[q];
        float4 e0 = ef4[q * 4 + 0];
        float4 e1 = ef4[q * 4 + 1];
        float4 e2 = ef4[q * 4 + 2];
        float4 e3 = ef4[q * 4 + 3];
        uint4 w;
        w.w = 0u;

        w.x = (unsigned int)sv.x; w.y = pack_h2(e0.x, e0.y); w.z = pack_h2(e0.z, e0.w);
        g_sorted[g_off[dv.x] + rv.x] = w;
        w.x = (unsigned int)sv.y; w.y = pack_h2(e1.x, e1.y); w.z = pack_h2(e1.z, e1.w);
        g_sorted[g_off[dv.y] + rv.y] = w;
        w.x = (unsigned int)sv.z; w.y = pack_h2(e2.x, e2.y); w.z = pack_h2(e2.z, e2.w);
        g_sorted[g_off[dv.z] + rv.z] = w;
        w.x = (unsigned int)sv.w; w.y = pack_h2(e3.x, e3.y); w.z = pack_h2(e3.z, e3.w);
        g_sorted[g_off[dv.w] + rv.w] = w;
    }
}

// ---------------- layer 1 (R8 proven form): edge stream + one fp16 nf gather ----------------
__global__ void node1_kernel(const float* __restrict__ W1a, const float* __restrict__ b1a,
                             const float* __restrict__ W1b, const float* __restrict__ b1b) {
    __shared__ float sW1a[11 * 32];
    __shared__ float sW1b[32 * 32];
    __shared__ float sb1a[32];
    __shared__ float sb1b[32];
    int tid = threadIdx.x;
    for (int k = tid; k < 11 * 32; k += blockDim.x) sW1a[k] = W1a[k];
    for (int k = tid; k < 32 * 32; k += blockDim.x) sW1b[k] = W1b[k];
    if (tid < 32) { sb1a[tid] = b1a[tid]; sb1b[tid] = b1b[tid]; }
    __syncthreads();

    int warp = tid >> 5;
    int lane = tid & 31;
    int n = blockIdx.x * 8 + warp;

    int start = g_off[n];
    int deg   = g_count[n];

    float acc[11];
#pragma unroll
    for (int k = 0; k < 11; k++) acc[k] = 0.0f;

    const uint4* nfq = (const uint4*)g_nfh;
    for (int j = lane; j < deg; j += 32) {
        uint4 p = __ldg(&g_sorted[start + j]);   // coalesced 16B stream
        float2 e01 = __half22float2(*(__half2*)&p.y);
        float2 e23 = __half22float2(*(__half2*)&p.z);
        acc[0] += e01.x; acc[1] += e01.y; acc[2] += e23.x; acc[3] += e23.y;
        uint4 nf = __ldg(&nfq[p.x]);             // ONE 16B gather (L2-resident)
        float2 f0 = __half22float2(*(__half2*)&nf.x);
        float2 f1 = __half22float2(*(__half2*)&nf.y);
        float2 f2 = __half22float2(*(__half2*)&nf.z);
        float2 f3 = __half22float2(*(__half2*)&nf.w);
        acc[4] += f0.x; acc[5] += f0.y;
        acc[6] += f1.x; acc[7] += f1.y;
        acc[8] += f2.x; acc[9] += f2.y;
        acc[10] += f3.x;
    }

#pragma unroll
    for (int off = 16; off; off >>= 1) {
#pragma unroll
        for (int k = 0; k < 11; k++)
            acc[k] += __shfl_xor_sync(0xffffffffu, acc[k], off);
    }

    float invd = 1.0f / fmaxf((float)deg, 1.0f);

    float y = sb1a[lane];
#pragma unroll
    for (int k = 0; k < 11; k++)
        y = fmaf(acc[k] * invd, sW1a[k * 32 + lane], y);
    y = fmaxf(y, 0.0f);

    float z = sb1b[lane];
#pragma unroll
    for (int k = 0; k < 32; k++) {
        float yk = __shfl_sync(0xffffffffu, y, k);
        z = fmaf(yk, sW1b[k * 32 + lane], z);
    }
    z = fmaxf(z, 0.0f);

    g_h1h[n * 32 + lane] = __float2half_rn(z);
}

// ---------------- layer 2: 32-edge rounds, 4 LDG.128 in flight + smem float4 MLP ----------------
__global__ void __launch_bounds__(256, 6) node2_kernel(
        const float* __restrict__ W2a, const float* __restrict__ b2a,
        const float* __restrict__ W2b, const float* __restrict__ b2b,
        const int* __restrict__ graph_ids) {
    __shared__ float4 sWaT[256];    // [kq*32+lane] = {W2a[4kq+j][lane]}
    __shared__ float4 sWbT[256];
    __shared__ float  sb2a[32];
    __shared__ float  sb2b[32];
    __shared__ float  sX[8][32];
    int tid = threadIdx.x;
    for (int idx0 = tid; idx0 < 256; idx0 += blockDim.x) {
        int kq = idx0 >> 5, ln = idx0 & 31;
        sWaT[kq * 32 + ln] = make_float4(W2a[(4 * kq + 0) * 32 + ln],
                                         W2a[(4 * kq + 1) * 32 + ln],
                                         W2a[(4 * kq + 2) * 32 + ln],
                                         W2a[(4 * kq + 3) * 32 + ln]);
        sWbT[kq * 32 + ln] = make_float4(W2b[(4 * kq + 0) * 32 + ln],
                                         W2b[(4 * kq + 1) * 32 + ln],
                                         W2b[(4 * kq + 2) * 32 + ln],
                                         W2b[(4 * kq + 3) * 32 + ln]);
    }
    if (tid < 32) { sb2a[tid] = b2a[tid]; sb2b[tid] = b2b[tid]; }
    __syncthreads();

    int warp = tid >> 5;
    int lane = tid & 31;
    int n = blockIdx.x * 8 + warp;

    int start = g_off[n];
    int deg   = g_count[n];

    int q = lane & 3;    // 16B quarter of the 64B h1 row (features q*8 .. q*8+7)
    int e = lane >> 2;   // edge-within-group 0..7
    const uint4* h1q = (const uint4*)g_h1h;

    float2 a0 = make_float2(0.f, 0.f);
    float2 a1 = make_float2(0.f, 0.f);
    float2 a2 = make_float2(0.f, 0.f);
    float2 a3 = make_float2(0.f, 0.f);

    // 32-edge rounds: full-warp index load (prefetched), 4 independent LDG.128 per round
    int idx = 0;
    if (deg > 0) idx = (int)g_sorted[start + lane].x;        // slack-safe
    for (int j = 0; j < deg; j += 32) {
        int nidx = 0;
        if (j + 32 < deg)
            nidx = (int)g_sorted[start + j + 32 + lane].x;   // prefetch next round
        // resolve 4 group indices first (independent), then issue 4 gathers back-to-back
        int s0 = __shfl_sync(0xffffffffu, idx,  0 + e);
        int s1 = __shfl_sync(0xffffffffu, idx,  8 + e);
        int s2 = __shfl_sync(0xffffffffu, idx, 16 + e);
        int s3 = __shfl_sync(0xffffffffu, idx, 24 + e);
        s0 = (j + 0 + e  < deg) ? s0 : NN;
        s1 = (j + 8 + e  < deg) ? s1 : NN;
        s2 = (j + 16 + e < deg) ? s2 : NN;
        s3 = (j + 24 + e < deg) ? s3 : NN;
        uint4 v0 = __ldg(&h1q[s0 * 4 + q]);   // 4 LDG.128 in flight
        uint4 v1 = __ldg(&h1q[s1 * 4 + q]);
        uint4 v2 = __ldg(&h1q[s2 * 4 + q]);
        uint4 v3 = __ldg(&h1q[s3 * 4 + q]);
        float2 f;
        f = __half22float2(*(__half2*)&v0.x); a0.x += f.x; a0.y += f.y;
        f = __half22float2(*(__half2*)&v0.y); a1.x += f.x; a1.y += f.y;
        f = __half22float2(*(__half2*)&v0.z); a2.x += f.x; a2.y += f.y;
        f = __half22float2(*(__half2*)&v0.w); a3.x += f.x; a3.y += f.y;
        f = __half22float2(*(__half2*)&v1.x); a0.x += f.x; a0.y += f.y;
        f = __half22float2(*(__half2*)&v1.y); a1.x += f.x; a1.y += f.y;
        f = __half22float2(*(__half2*)&v1.z); a2.x += f.x; a2.y += f.y;
        f = __half22float2(*(__half2*)&v1.w); a3.x += f.x; a3.y += f.y;
        f = __half22float2(*(__half2*)&v2.x); a0.x += f.x; a0.y += f.y;
        f = __half22float2(*(__half2*)&v2.y); a1.x += f.x; a1.y += f.y;
        f = __half22float2(*(__half2*)&v2.z); a2.x += f.x; a2.y += f.y;
        f = __half22float2(*(__half2*)&v2.w); a3.x += f.x; a3.y += f.y;
        f = __half22float2(*(__half2*)&v3.x); a0.x += f.x; a0.y += f.y;
        f = __half22float2(*(__half2*)&v3.y); a1.x += f.x; a1.y += f.y;
        f = __half22float2(*(__half2*)&v3.z); a2.x += f.x; a2.y += f.y;
        f = __half22float2(*(__half2*)&v3.w); a3.x += f.x; a3.y += f.y;
        idx = nidx;
    }

    // reduce across the 8 edge-lanes sharing this q (partners at xor 4, 8, 16)
#pragma unroll
    for (int off = 4; off <= 16; off <<= 1) {
        a0.x += __shfl_xor_sync(0xffffffffu, a0.x, off);
        a0.y += __shfl_xor_sync(0xffffffffu, a0.y, off);
        a1.x += __shfl_xor_sync(0xffffffffu, a1.x, off);
        a1.y += __shfl_xor_sync(0xffffffffu, a1.y, off);
        a2.x += __shfl_xor_sync(0xffffffffu, a2.x, off);
        a2.y += __shfl_xor_sync(0xffffffffu, a2.y, off);
        a3.x += __shfl_xor_sync(0xffffffffu, a3.x, off);
        a3.y += __shfl_xor_sync(0xffffffffu, a3.y, off);
    }

    // lanes 0-3 (e==0) publish the scaled mean: sX[warp][q*8+k]
    float invd = 1.0f / fmaxf((float)deg, 1.0f);
    if (e == 0) {
        sX[warp][q * 8 + 0] = a0.x * invd;
        sX[warp][q * 8 + 1] = a0.y * invd;
        sX[warp][q * 8 + 2] = a1.x * invd;
        sX[warp][q * 8 + 3] = a1.y * invd;
        sX[warp][q * 8 + 4] = a2.x * invd;
        sX[warp][q * 8 + 5] = a2.y * invd;
        sX[warp][q * 8 + 6] = a3.x * invd;
        sX[warp][q * 8 + 7] = a3.y * invd;
    }
    __syncwarp();

    // MLP layer a (x staged in sX)
    float y = sb2a[lane];
#pragma unroll
    for (int kq = 0; kq < 8; kq++) {
        float4 xv = *(const float4*)&sX[warp][kq * 4];
        float4 w  = sWaT[kq * 32 + lane];
        y = fmaf(xv.x, w.x, y);
        y = fmaf(xv.y, w.y, y);
        y = fmaf(xv.z, w.z, y);
        y = fmaf(xv.w, w.w, y);
    }
    y = fmaxf(y, 0.0f);

    // MLP layer b
    __syncwarp();
    sX[warp][lane] = y;
    __syncwarp();
    float z = sb2b[lane];
#pragma unroll
    for (int kq = 0; kq < 8; kq++) {
        float4 xv = *(const float4*)&sX[warp][kq * 4];
        float4 w  = sWbT[kq * 32 + lane];
        z = fmaf(xv.x, w.x, z);
        z = fmaf(xv.y, w.y, z);
        z = fmaf(xv.z, w.z, z);
        z = fmaf(xv.w, w.w, z);
    }
    z = fmaxf(z, 0.0f);  // >= 0 -> int-compare atomicMax is order-safe

    int g = graph_ids[n];
    atomicMax((int*)&g_pooled[g * 32 + lane], __float_as_int(z));
}

// ---------------- classifier head ----------------
__global__ void head_kernel(const float* __restrict__ Wm1, const float* __restrict__ bm1,
                            const float* __restrict__ Wm2, const float* __restrict__ bm2,
                            float* __restrict__ out) {
    int g = threadIdx.x;
    if (g >= NG) return;
    float p[32];
#pragma unroll
    for (int k = 0; k < 32; k++) p[k] = g_pooled[g * 32 + k];
    float hid[16];
#pragma unroll
    for (int jj = 0; jj < 16; jj++) {
        float a = bm1[jj];
#pragma unroll
        for (int k = 0; k < 32; k++) a = fmaf(p[k], Wm1[k * 16 + jj], a);
        hid[jj] = fmaxf(a, 0.0f);
    }
    float l0 = bm2[0], l1 = bm2[1];
#pragma unroll
    for (int jj = 0; jj < 16; jj++) {
        l0 = fmaf(hid[jj], Wm2[jj * 2 + 0], l0);
        l1 = fmaf(hid[jj], Wm2[jj * 2 + 1], l1);
    }
    float m = fmaxf(l0, l1);
    float e0 = expf(l0 - m);
    float e1 = expf(l1 - m);
    float inv = 1.0f / (e0 + e1);
    out[g * 2 + 0] = e0 * inv;
    out[g * 2 + 1] = e1 * inv;
}

extern "C" void kernel_launch(void* const* d_in, const int* in_sizes, int n_in,
                              void* d_out, int out_size) {
    const float* node_feat = (const float*)d_in[0];
    const float* edge_feat = (const float*)d_in[1];
    const int*   src       = (const int*)d_in[2];
    const int*   dst       = (const int*)d_in[3];
    const int*   graph_ids = (const int*)d_in[4];
    const float* W1a = (const float*)d_in[5];
    const float* b1a = (const float*)d_in[6];
    const float* W1b = (const float*)d_in[7];
    const float* b1b = (const float*)d_in[8];
    const float* W2a = (const float*)d_in[9];
    const float* b2a = (const float*)d_in[10];
    const float* W2b = (const float*)d_in[11];
    const float* b2b = (const float*)d_in[12];
    const float* Wm1 = (const float*)d_in[13];
    const float* bm1 = (const float*)d_in[14];
    const float* Wm2 = (const float*)d_in[15];
    const float* bm2 = (const float*)d_in[16];
    float* out = (float*)d_out;

    setup_kernel<<<(NN * 8 + 255) / 256, 256>>>(node_feat);
    sort_kernel<<<NB_SCAN, 256>>>((const int4*)src, (const int4*)dst,
                                  (const float4*)edge_feat);
    node1_kernel<<<NN / 8, 256>>>(W1a, b1a, W1b, b1b);
    node2_kernel<<<NN / 8, 256>>>(W2a, b2a, W2b, b2b, graph_ids);
    head_kernel<<<1, 64>>>(Wm1, bm1, Wm2, bm2, out);
}